// round 4
// baseline (speedup 1.0000x reference)
#include <cuda_runtime.h>
#include <math.h>

#define SEQ   2048
#define BATCH 2
#define HID   1024
#define NHEAD 8
#define HDIM  128
#define ROWS  (BATCH*SEQ)   /* 4096 */
#define N6    (6*HID)       /* 6144 */
#define N3    (3*HID)       /* 3072 */

/* ---------------- scratch (device globals; no allocation allowed) ------- */
__device__ float g_fused[(size_t)ROWS*N6];   /* silu(X @ W_qkvu)   ~100 MB */
__device__ float g_qr[(size_t)ROWS*HID];     /* q with RoPE applied        */
__device__ float g_kr[(size_t)ROWS*HID];     /* k with RoPE applied        */
__device__ float g_comb[(size_t)ROWS*N3];    /* combined * gated   ~50 MB  */
__device__ float g_y[(size_t)ROWS*HID];      /* pre-RMSNorm                */
__device__ int   g_mask_int;                 /* 1 if mask is int32, 0 bool */

/* ---------------- mask dtype detector ---------------------------------- */
__global__ void mask_detect_kernel(const unsigned char* __restrict__ mask)
{
    __shared__ int cnt;
    if (threadIdx.x == 0) cnt = 0;
    __syncthreads();
    int c = 0;
    for (int i = threadIdx.x; i < 16384; i += 256) c += (mask[i] != 0);
    atomicAdd(&cnt, c);
    __syncthreads();
    if (threadIdx.x == 0) {
        /* bool: ~50% nonzero bytes; int32 0/1: ~12.5% nonzero bytes */
        g_mask_int = (cnt < 4096) ? 1 : 0;
    }
}

/* ---------------- generic 128x128x16 SGEMM, 8x8 micro-tiles ------------ */
/* EPI 0: C = silu(A@B)          (QKVU projection)                         */
/* EPI 1: C = A@B + bias + resid (output projection + residual)            */
template<int KDIM, int NDIM, int EPI>
__global__ __launch_bounds__(256)
void gemm_kernel(const float* __restrict__ A, const float* __restrict__ Bm,
                 float* __restrict__ C,
                 const float* __restrict__ bias, const float* __restrict__ resid)
{
    __shared__ float As[16][128];   /* k-major (transposed A tile) */
    __shared__ float Bs[16][128];

    const int tid  = threadIdx.x;
    const int tx   = tid & 15, ty = tid >> 4;
    const int arow = tid >> 2,  acol = (tid & 3) << 2;
    const int brow = tid >> 5,  bcol = (tid & 31) << 2;

    const float* Ap = A + (size_t)(blockIdx.y * 128) * KDIM;
    const float* Bp = Bm + blockIdx.x * 128;

    float acc[8][8];
#pragma unroll
    for (int i = 0; i < 8; i++)
#pragma unroll
        for (int j = 0; j < 8; j++) acc[i][j] = 0.f;

    for (int k0 = 0; k0 < KDIM; k0 += 16) {
#pragma unroll
        for (int i = 0; i < 2; i++) {
            int r = arow + i * 64;
            float4 v = *(const float4*)(Ap + (size_t)r * KDIM + (k0 + acol));
            As[acol+0][r] = v.x; As[acol+1][r] = v.y;
            As[acol+2][r] = v.z; As[acol+3][r] = v.w;
        }
#pragma unroll
        for (int i = 0; i < 2; i++) {
            int r = brow + i * 8;
            *(float4*)&Bs[r][bcol] = *(const float4*)(Bp + (size_t)(k0 + r) * NDIM + bcol);
        }
        __syncthreads();
#pragma unroll
        for (int kk = 0; kk < 16; kk++) {
            float a[8], b[8];
#pragma unroll
            for (int i = 0; i < 4; i++) { a[i] = As[kk][ty*4+i]; a[i+4] = As[kk][64+ty*4+i]; }
#pragma unroll
            for (int j = 0; j < 4; j++) { b[j] = Bs[kk][tx*4+j]; b[j+4] = Bs[kk][64+tx*4+j]; }
#pragma unroll
            for (int i = 0; i < 8; i++)
#pragma unroll
                for (int j = 0; j < 8; j++)
                    acc[i][j] = fmaf(a[i], b[j], acc[i][j]);
        }
        __syncthreads();
    }

#pragma unroll
    for (int i = 0; i < 8; i++) {
        int m = (i < 4) ? (ty*4 + i) : (64 + ty*4 + (i - 4));
        size_t grow = (size_t)blockIdx.y * 128 + m;
#pragma unroll
        for (int jj = 0; jj < 2; jj++) {
            int n = (jj == 0) ? (tx*4) : (64 + tx*4);
            size_t gcol = (size_t)blockIdx.x * 128 + n;
            float v0 = acc[i][jj*4+0], v1 = acc[i][jj*4+1];
            float v2 = acc[i][jj*4+2], v3 = acc[i][jj*4+3];
            float4 o;
            if (EPI == 0) {
                o.x = v0 / (1.f + expf(-v0));
                o.y = v1 / (1.f + expf(-v1));
                o.z = v2 / (1.f + expf(-v2));
                o.w = v3 / (1.f + expf(-v3));
            } else {
                size_t rb = grow * NDIM + gcol;
                o.x = v0 + bias[gcol+0] + resid[rb+0];
                o.y = v1 + bias[gcol+1] + resid[rb+1];
                o.z = v2 + bias[gcol+2] + resid[rb+2];
                o.w = v3 + bias[gcol+3] + resid[rb+3];
            }
            *(float4*)&C[grow * NDIM + gcol] = o;
        }
    }
}

/* ---------------- RoPE: q_rope, k_rope from fused q/k slices ------------ */
__global__ __launch_bounds__(256)
void rope_kernel(const float* __restrict__ fused,
                 float* __restrict__ qr, float* __restrict__ kr)
{
    int idx = blockIdx.x * 256 + threadIdx.x;     /* ROWS*NHEAD*64 = 2M */
    if (idx >= ROWS * NHEAD * 64) return;
    int i   = idx & 63;
    int h   = (idx >> 6) & 7;
    int row = idx >> 9;
    int pos = row & (SEQ - 1);

    float inv = 1.0f / powf(10000.0f, (2.0f * (float)i) / 128.0f);
    float f = (float)pos * inv;
    float s, c;
    sincosf(f, &s, &c);

    const float* base = fused + (size_t)row * N6;
    int off = h * 128 + 2 * i;
    float q0 = base[4*HID + off], q1 = base[4*HID + off + 1];
    float k0 = base[5*HID + off], k1 = base[5*HID + off + 1];
    size_t o = (size_t)row * HID + off;
    qr[o]   = q0 * c - q1 * s;
    qr[o+1] = q1 * c + q0 * s;
    kr[o]   = k0 * c - k1 * s;
    kr[o+1] = k1 * c + k0 * s;
}

/* ---------------- fused 3-way attention --------------------------------- */
/* per (b,h,n-tile of 32): stream 32-row m-tiles; phase A = 32x32 scores    */
/* (plain relu-QK, rope relu-QK, masked bias) -> smem; phase B = S @ V.     */
/* Epilogue multiplies by `gated` and writes g_comb in the reference's      */
/* per-head-interleaved layout: col = h*384 + section*128 + d.              */
#define LDT  132   /* 128 + 4 pad: conflict-free strided float4 access */
#define LDS_ 33

__global__ __launch_bounds__(256)
void attn_kernel(const unsigned char* __restrict__ mask,
                 const float* __restrict__ bias,
                 float* __restrict__ comb)
{
    extern __shared__ float sm[];
    float* q_s  = sm;                 /* [32][132] */
    float* qr_s = q_s  + 32 * LDT;
    float* k_s  = qr_s + 32 * LDT;
    float* kr_s = k_s  + 32 * LDT;
    float* v_s  = kr_s + 32 * LDT;
    float* sp   = v_s  + 32 * LDT;    /* [32][33] plain scores  */
    float* sr   = sp   + 32 * LDS_;   /* rope scores            */
    float* st   = sr   + 32 * LDS_;   /* ts (masked bias)       */
    float* mk   = st   + 32 * LDS_;   /* mask as float          */

    const int b  = blockIdx.z, h = blockIdx.y;
    const int n0 = blockIdx.x * 32;
    const int tid = threadIdx.x;
    const int tx = tid & 15, ty = tid >> 4;
    const int pn = tid >> 3;            /* phase-B / load row 0..31 */
    const int pc = (tid & 7) << 2;      /* phase-B word base        */
    const float inv_s = 1.0f / (float)SEQ;
    const int mint = g_mask_int;

    /* load q / q_rope tiles (persistent) */
    {
        size_t rowq = (size_t)(b * SEQ + n0 + pn);
        const float* qg  = g_fused + rowq * N6 + 4*HID + h*128;
        const float* qrg = g_qr    + rowq * HID + h*128;
#pragma unroll
        for (int c = 0; c < 4; c++) {
            int d = pc + 32 * c;
            *(float4*)&q_s [pn*LDT + d] = *(const float4*)&qg[d];
            *(float4*)&qr_s[pn*LDT + d] = *(const float4*)&qrg[d];
        }
    }

    float4 accR[4], accT[4], accP[4];
#pragma unroll
    for (int r = 0; r < 4; r++) {
        accR[r] = make_float4(0,0,0,0);
        accT[r] = make_float4(0,0,0,0);
        accP[r] = make_float4(0,0,0,0);
    }

    for (int m0 = 0; m0 < SEQ; m0 += 32) {
        __syncthreads();   /* prior phase B done before overwriting tiles */

        /* load k / k_rope / v tiles */
        {
            size_t rowm = (size_t)(b * SEQ + m0 + pn);
            const float* kg  = g_fused + rowm * N6 + 5*HID + h*128;
            const float* vg  = g_fused + rowm * N6 + 3*HID + h*128;
            const float* krg = g_kr    + rowm * HID + h*128;
#pragma unroll
            for (int c = 0; c < 4; c++) {
                int d = pc + 32 * c;
                *(float4*)&k_s [pn*LDT + d] = *(const float4*)&kg[d];
                *(float4*)&kr_s[pn*LDT + d] = *(const float4*)&krg[d];
                *(float4*)&v_s [pn*LDT + d] = *(const float4*)&vg[d];
            }
            /* mask + bias tile [32n][32m]; 4 m-entries per thread */
            size_t gi = ((size_t)b * SEQ + (n0 + pn)) * SEQ + m0 + pc;
            float4 bv = *(const float4*)&bias[gi];
            float f0, f1, f2, f3;
            if (mint) {
                int4 mi = *(const int4*)&((const int*)mask)[gi];
                f0 = mi.x ? 1.f : 0.f; f1 = mi.y ? 1.f : 0.f;
                f2 = mi.z ? 1.f : 0.f; f3 = mi.w ? 1.f : 0.f;
            } else {
                uchar4 mu = *(const uchar4*)&mask[gi];
                f0 = mu.x ? 1.f : 0.f; f1 = mu.y ? 1.f : 0.f;
                f2 = mu.z ? 1.f : 0.f; f3 = mu.w ? 1.f : 0.f;
            }
            int sb = pn * LDS_ + pc;
            mk[sb+0] = f0; mk[sb+1] = f1; mk[sb+2] = f2; mk[sb+3] = f3;
            st[sb+0] = f0 * bv.x; st[sb+1] = f1 * bv.y;
            st[sb+2] = f2 * bv.z; st[sb+3] = f3 * bv.w;
        }
        __syncthreads();

        /* phase A: 2x2 micro-tile scores (rows ty,ty+16 x cols tx,tx+16) */
        float dp00=0,dp01=0,dp10=0,dp11=0;
        float dr00=0,dr01=0,dr10=0,dr11=0;
#pragma unroll 4
        for (int d4 = 0; d4 < 32; d4++) {
            int o = d4 << 2;
            float4 a0 = *(const float4*)&q_s[ ty      *LDT + o];
            float4 a1 = *(const float4*)&q_s[(ty+16)  *LDT + o];
            float4 b0 = *(const float4*)&k_s[ tx      *LDT + o];
            float4 b1 = *(const float4*)&k_s[(tx+16)  *LDT + o];
            dp00 += a0.x*b0.x + a0.y*b0.y + a0.z*b0.z + a0.w*b0.w;
            dp01 += a0.x*b1.x + a0.y*b1.y + a0.z*b1.z + a0.w*b1.w;
            dp10 += a1.x*b0.x + a1.y*b0.y + a1.z*b0.z + a1.w*b0.w;
            dp11 += a1.x*b1.x + a1.y*b1.y + a1.z*b1.z + a1.w*b1.w;
            float4 c0 = *(const float4*)&qr_s[ ty     *LDT + o];
            float4 c1 = *(const float4*)&qr_s[(ty+16) *LDT + o];
            float4 e0 = *(const float4*)&kr_s[ tx     *LDT + o];
            float4 e1 = *(const float4*)&kr_s[(tx+16) *LDT + o];
            dr00 += c0.x*e0.x + c0.y*e0.y + c0.z*e0.z + c0.w*e0.w;
            dr01 += c0.x*e1.x + c0.y*e1.y + c0.z*e1.z + c0.w*e1.w;
            dr10 += c1.x*e0.x + c1.y*e0.y + c1.z*e0.z + c1.w*e0.w;
            dr11 += c1.x*e1.x + c1.y*e1.y + c1.z*e1.z + c1.w*e1.w;
        }
        {
            float m00 = mk[ ty     *LDS_ + tx     ];
            float m01 = mk[ ty     *LDS_ + tx + 16];
            float m10 = mk[(ty+16) *LDS_ + tx     ];
            float m11 = mk[(ty+16) *LDS_ + tx + 16];
            sp[ ty     *LDS_ + tx     ] = m00 * fmaxf(dp00, 0.f) * inv_s;
            sp[ ty     *LDS_ + tx + 16] = m01 * fmaxf(dp01, 0.f) * inv_s;
            sp[(ty+16) *LDS_ + tx     ] = m10 * fmaxf(dp10, 0.f) * inv_s;
            sp[(ty+16) *LDS_ + tx + 16] = m11 * fmaxf(dp11, 0.f) * inv_s;
            sr[ ty     *LDS_ + tx     ] = m00 * fmaxf(dr00, 0.f) * inv_s;
            sr[ ty     *LDS_ + tx + 16] = m01 * fmaxf(dr01, 0.f) * inv_s;
            sr[(ty+16) *LDS_ + tx     ] = m10 * fmaxf(dr10, 0.f) * inv_s;
            sr[(ty+16) *LDS_ + tx + 16] = m11 * fmaxf(dr11, 0.f) * inv_s;
        }
        __syncthreads();

        /* phase B: out[n, d] += scores @ V  (three accumulators) */
#pragma unroll 4
        for (int m = 0; m < 32; m++) {
            float s_r = sr[pn*LDS_ + m];
            float s_t = st[pn*LDS_ + m];
            float s_p = sp[pn*LDS_ + m];
            const float* vp = &v_s[m*LDT + pc];
#pragma unroll
            for (int r = 0; r < 4; r++) {
                float4 v4 = *(const float4*)(vp + 32 * r);
                accR[r].x = fmaf(s_r, v4.x, accR[r].x);
                accR[r].y = fmaf(s_r, v4.y, accR[r].y);
                accR[r].z = fmaf(s_r, v4.z, accR[r].z);
                accR[r].w = fmaf(s_r, v4.w, accR[r].w);
                accT[r].x = fmaf(s_t, v4.x, accT[r].x);
                accT[r].y = fmaf(s_t, v4.y, accT[r].y);
                accT[r].z = fmaf(s_t, v4.z, accT[r].z);
                accT[r].w = fmaf(s_t, v4.w, accT[r].w);
                accP[r].x = fmaf(s_p, v4.x, accP[r].x);
                accP[r].y = fmaf(s_p, v4.y, accP[r].y);
                accP[r].z = fmaf(s_p, v4.z, accP[r].z);
                accP[r].w = fmaf(s_p, v4.w, accP[r].w);
            }
        }
    }

    /* epilogue: multiply by gated, write combined layout.                  */
    /* Reference: concat([rope,ts,plain], axis=-1) on (B,S,nh,hd) BEFORE    */
    /* the reshape -> per-row col = h*(3*HDIM) + section*HDIM + d.          */
    {
        size_t row = (size_t)(b * SEQ + n0 + pn);
        const float* gate = g_fused + row * N6;   /* gated = cols 0..3071 */
        float* outp = comb + row * N3;
#pragma unroll
        for (int r = 0; r < 4; r++) {
            int d = pc + 32 * r;
            int cR = h*384 +   0 + d;   /* rope  section */
            int cT = h*384 + 128 + d;   /* ts    section */
            int cP = h*384 + 256 + d;   /* plain section */
            float4 gR = *(const float4*)&gate[cR];
            float4 gT = *(const float4*)&gate[cT];
            float4 gP = *(const float4*)&gate[cP];
            float4 oR, oT, oP;
            oR.x = accR[r].x * gR.x; oR.y = accR[r].y * gR.y;
            oR.z = accR[r].z * gR.z; oR.w = accR[r].w * gR.w;
            oT.x = accT[r].x * gT.x; oT.y = accT[r].y * gT.y;
            oT.z = accT[r].z * gT.z; oT.w = accT[r].w * gT.w;
            oP.x = accP[r].x * gP.x; oP.y = accP[r].y * gP.y;
            oP.z = accP[r].z * gP.z; oP.w = accP[r].w * gP.w;
            *(float4*)&outp[cR] = oR;
            *(float4*)&outp[cT] = oT;
            *(float4*)&outp[cP] = oP;
        }
    }
}

/* ---------------- RMSNorm --------------------------------------------- */
__global__ __launch_bounds__(256)
void rms_kernel(const float* __restrict__ y, const float* __restrict__ w,
                float* __restrict__ out)
{
    __shared__ float sh[8];
    __shared__ float tot;
    int row = blockIdx.x;
    const float* yr = y + (size_t)row * HID;
    float ss = 0.f;
    for (int i = threadIdx.x; i < HID; i += 256) {
        float v = yr[i];
        ss = fmaf(v, v, ss);
    }
#pragma unroll
    for (int o = 16; o > 0; o >>= 1) ss += __shfl_down_sync(0xffffffffu, ss, o);
    if ((threadIdx.x & 31) == 0) sh[threadIdx.x >> 5] = ss;
    __syncthreads();
    if (threadIdx.x == 0) {
        float t = 0.f;
#pragma unroll
        for (int i = 0; i < 8; i++) t += sh[i];
        tot = rsqrtf(t / (float)HID + 1e-6f);
    }
    __syncthreads();
    float r = tot;
    for (int i = threadIdx.x; i < HID; i += 256)
        out[(size_t)row * HID + i] = yr[i] * r * w[i];
}

/* ---------------- launch ----------------------------------------------- */
extern "C" void kernel_launch(void* const* d_in, const int* in_sizes, int n_in,
                              void* d_out, int out_size)
{
    const float*         hidden = (const float*)d_in[0];
    const unsigned char* mask   = (const unsigned char*)d_in[1];
    const float*         bias   = (const float*)d_in[2];
    const float*         Wqkvu  = (const float*)d_in[3];
    const float*         Wout   = (const float*)d_in[4];
    const float*         bout   = (const float*)d_in[5];
    const float*         rmsw   = (const float*)d_in[6];
    float*               out    = (float*)d_out;

    float *fused, *qrp, *krp, *comb, *yp;
    cudaGetSymbolAddress((void**)&fused, g_fused);
    cudaGetSymbolAddress((void**)&qrp,   g_qr);
    cudaGetSymbolAddress((void**)&krp,   g_kr);
    cudaGetSymbolAddress((void**)&comb,  g_comb);
    cudaGetSymbolAddress((void**)&yp,    g_y);

    const size_t ATTN_SMEM = (size_t)(5*32*LDT + 4*32*LDS_) * sizeof(float); /* ~101 KB */
    cudaFuncSetAttribute(attn_kernel, cudaFuncAttributeMaxDynamicSharedMemorySize,
                         (int)ATTN_SMEM);

    mask_detect_kernel<<<1, 256>>>(mask);

    /* fused = silu(hidden @ W_qkvu) : 4096 x 6144, K=1024 */
    gemm_kernel<1024, 6144, 0><<<dim3(48, 32), 256>>>(hidden, Wqkvu, fused,
                                                      nullptr, nullptr);

    /* RoPE on q,k slices */
    rope_kernel<<<(ROWS*NHEAD*64)/256, 256>>>(fused, qrp, krp);

    /* fused 3-way attention -> g_comb (already gated) */
    attn_kernel<<<dim3(SEQ/32, NHEAD, BATCH), 256, ATTN_SMEM>>>(mask, bias, comb);

    /* y = comb @ W_out + b_out + hidden : 4096 x 1024, K=3072 */
    gemm_kernel<3072, 1024, 1><<<dim3(8, 32), 256>>>(comb, Wout, yp, bout, hidden);

    /* out = RMSNorm(y) * rms_weight */
    rms_kernel<<<ROWS, 256>>>(yp, rmsw, out);
}

// round 6
// speedup vs baseline: 1.2277x; 1.2277x over previous
#include <cuda_runtime.h>
#include <cuda_bf16.h>
#include <cstdint>
#include <math.h>

#define SEQ   2048
#define BATCH 2
#define HID   1024
#define NHEAD 8
#define HDIM  128
#define ROWS  (BATCH*SEQ)   /* 4096 */
#define N6    (6*HID)       /* 6144 */
#define N3    (3*HID)       /* 3072 */

/* ---------------- scratch (device globals; no allocation allowed) ------- */
__device__ float g_fused[(size_t)ROWS*N6];   /* silu(X @ W_qkvu)   ~100 MB */
__device__ float g_qr[(size_t)ROWS*HID];
__device__ float g_kr[(size_t)ROWS*HID];
__device__ float g_comb[(size_t)ROWS*N3];    /* combined * gated   ~50 MB  */
__device__ float g_y[(size_t)ROWS*HID];
__device__ int   g_mask_int;

/* bf16x2-split operands for mma.sync GEMMs */
__device__ __nv_bfloat16 g_ah[(size_t)ROWS*HID];    /* hidden hi          */
__device__ __nv_bfloat16 g_al[(size_t)ROWS*HID];    /* hidden lo          */
__device__ __nv_bfloat16 g_wqh[(size_t)N6*HID];     /* W_qkvu^T hi [n][k] */
__device__ __nv_bfloat16 g_wql[(size_t)N6*HID];
__device__ __nv_bfloat16 g_woh[(size_t)HID*N3];     /* W_out^T  hi [n][k] */
__device__ __nv_bfloat16 g_wol[(size_t)HID*N3];
__device__ __nv_bfloat16 g_ch[(size_t)ROWS*N3];     /* comb hi            */
__device__ __nv_bfloat16 g_cl[(size_t)ROWS*N3];     /* comb lo            */

/* ================= mma.sync helpers (sm_80+ path, works on sm_100) ===== */
__device__ __forceinline__ uint32_t smem_u32(const void* p) {
    uint32_t a;
    asm("{ .reg .u64 t; cvta.to.shared.u64 t, %1; cvt.u32.u64 %0, t; }"
        : "=r"(a) : "l"(p));
    return a;
}
__device__ __forceinline__ void ldm_x4(uint32_t* r, uint32_t addr) {
    asm volatile("ldmatrix.sync.aligned.m8n8.x4.shared.b16 {%0,%1,%2,%3}, [%4];"
                 : "=r"(r[0]), "=r"(r[1]), "=r"(r[2]), "=r"(r[3]) : "r"(addr));
}
__device__ __forceinline__ void mma_bf16(float& d0, float& d1, float& d2, float& d3,
                                         uint32_t a0, uint32_t a1, uint32_t a2, uint32_t a3,
                                         uint32_t b0, uint32_t b1) {
    asm volatile("mma.sync.aligned.m16n8k16.row.col.f32.bf16.bf16.f32 "
                 "{%0,%1,%2,%3},{%4,%5,%6,%7},{%8,%9},{%0,%1,%2,%3};"
                 : "+f"(d0), "+f"(d1), "+f"(d2), "+f"(d3)
                 : "r"(a0), "r"(a1), "r"(a2), "r"(a3), "r"(b0), "r"(b1));
}

/* ================= mma.sync GEMM: C[M,N] = A @ B^T ===================== */
/* A: [M][KDIM] k-major bf16 hi/lo.  B: [NDIM][KDIM] k-major bf16 hi/lo.   */
/* Block 128x128, BK=32, 8 warps (2m x 4n), warp tile 64x32.               */
/* EPI 0: silu.  EPI 1: + bias + resid.                                    */
#define TSTR 40   /* smem row stride in bf16: 32 data + 8 pad (80B) */

template<int KDIM, int NDIM, int EPI>
__global__ __launch_bounds__(256)
void mma_gemm(const __nv_bfloat16* __restrict__ Ah, const __nv_bfloat16* __restrict__ Al,
              const __nv_bfloat16* __restrict__ Bh, const __nv_bfloat16* __restrict__ Bl,
              float* __restrict__ C,
              const float* __restrict__ bias, const float* __restrict__ resid)
{
    __shared__ __nv_bfloat16 sAh[128*TSTR], sAl[128*TSTR];
    __shared__ __nv_bfloat16 sBh[128*TSTR], sBl[128*TSTR];

    const int tid  = threadIdx.x;
    const int lane = tid & 31, wid = tid >> 5;
    const int wm = wid >> 2, wn = wid & 3;         /* warp -> (m,n) */
    const int m0 = blockIdx.y * 128, n0 = blockIdx.x * 128;

    const uint32_t uAh = smem_u32(sAh), uAl = smem_u32(sAl);
    const uint32_t uBh = smem_u32(sBh), uBl = smem_u32(sBl);

    /* ldmatrix lane addressing offsets */
    const int a_r = (lane & 7) + ((lane >> 3) & 1) * 8;   /* row in 16-blk */
    const int a_c = (lane >> 4) * 8;                      /* col half      */
    const int b_r = (lane & 7) + ((lane >> 4) & 1) * 8;   /* n in 16-blk   */
    const int b_c = ((lane >> 3) & 1) * 8;                /* k half        */

    float acc[4][4][4];
#pragma unroll
    for (int i = 0; i < 4; i++)
#pragma unroll
        for (int j = 0; j < 4; j++)
#pragma unroll
            for (int r = 0; r < 4; r++) acc[i][j][r] = 0.f;

    for (int kc = 0; kc < KDIM; kc += 32) {
        __syncthreads();   /* previous iter's ldmatrix reads complete */
#pragma unroll
        for (int i = 0; i < 2; i++) {
            int idx = tid + 256 * i;          /* 512 16B-chunks per tile */
            int row = idx >> 2, seg = (idx & 3) << 3;   /* seg in bf16 */
            size_t ga = (size_t)(m0 + row) * KDIM + kc + seg;
            size_t gb = (size_t)(n0 + row) * KDIM + kc + seg;
            int so = row * TSTR + seg;
            *(uint4*)&sAh[so] = *(const uint4*)(Ah + ga);
            *(uint4*)&sAl[so] = *(const uint4*)(Al + ga);
            *(uint4*)&sBh[so] = *(const uint4*)(Bh + gb);
            *(uint4*)&sBl[so] = *(const uint4*)(Bl + gb);
        }
        __syncthreads();

#pragma unroll
        for (int k0 = 0; k0 < 32; k0 += 16) {
            uint32_t fAh[4][4], fAl[4][4], fB[2][4];

            /* pass 1: Ah * Bh */
#pragma unroll
            for (int mt = 0; mt < 4; mt++)
                ldm_x4(fAh[mt], uAh + (uint32_t)((wm*64 + mt*16 + a_r) * TSTR + k0 + a_c) * 2);
#pragma unroll
            for (int bp = 0; bp < 2; bp++)
                ldm_x4(fB[bp], uBh + (uint32_t)((wn*32 + bp*16 + b_r) * TSTR + k0 + b_c) * 2);
#pragma unroll
            for (int mt = 0; mt < 4; mt++)
#pragma unroll
                for (int nt = 0; nt < 4; nt++)
                    mma_bf16(acc[mt][nt][0], acc[mt][nt][1], acc[mt][nt][2], acc[mt][nt][3],
                             fAh[mt][0], fAh[mt][1], fAh[mt][2], fAh[mt][3],
                             fB[nt>>1][(nt&1)*2], fB[nt>>1][(nt&1)*2+1]);

            /* pass 2: Al * Bh (Bh frags still live) */
#pragma unroll
            for (int mt = 0; mt < 4; mt++)
                ldm_x4(fAl[mt], uAl + (uint32_t)((wm*64 + mt*16 + a_r) * TSTR + k0 + a_c) * 2);
#pragma unroll
            for (int mt = 0; mt < 4; mt++)
#pragma unroll
                for (int nt = 0; nt < 4; nt++)
                    mma_bf16(acc[mt][nt][0], acc[mt][nt][1], acc[mt][nt][2], acc[mt][nt][3],
                             fAl[mt][0], fAl[mt][1], fAl[mt][2], fAl[mt][3],
                             fB[nt>>1][(nt&1)*2], fB[nt>>1][(nt&1)*2+1]);

            /* pass 3: Ah * Bl (overwrite B frags) */
#pragma unroll
            for (int bp = 0; bp < 2; bp++)
                ldm_x4(fB[bp], uBl + (uint32_t)((wn*32 + bp*16 + b_r) * TSTR + k0 + b_c) * 2);
#pragma unroll
            for (int mt = 0; mt < 4; mt++)
#pragma unroll
                for (int nt = 0; nt < 4; nt++)
                    mma_bf16(acc[mt][nt][0], acc[mt][nt][1], acc[mt][nt][2], acc[mt][nt][3],
                             fAh[mt][0], fAh[mt][1], fAh[mt][2], fAh[mt][3],
                             fB[nt>>1][(nt&1)*2], fB[nt>>1][(nt&1)*2+1]);
        }
    }

    /* epilogue straight from registers: d0,d1 = row g, cols 2t,2t+1;      */
    /* d2,d3 = row g+8.                                                    */
    const int er = lane >> 2, ec = (lane & 3) * 2;
#pragma unroll
    for (int mt = 0; mt < 4; mt++) {
#pragma unroll
        for (int nt = 0; nt < 4; nt++) {
            int col = n0 + wn*32 + nt*8 + ec;
#pragma unroll
            for (int half = 0; half < 2; half++) {
                size_t row = (size_t)(m0 + wm*64 + mt*16 + er + half*8);
                float v0 = acc[mt][nt][half*2 + 0];
                float v1 = acc[mt][nt][half*2 + 1];
                float2 o;
                if (EPI == 0) {
                    o.x = v0 / (1.f + expf(-v0));
                    o.y = v1 / (1.f + expf(-v1));
                } else {
                    size_t rb = row * NDIM + col;
                    o.x = v0 + bias[col+0] + resid[rb+0];
                    o.y = v1 + bias[col+1] + resid[rb+1];
                }
                *(float2*)&C[row * NDIM + col] = o;
            }
        }
    }
}

/* ============ fp32 -> bf16 hi/lo conversions =========================== */
__global__ __launch_bounds__(256)
void conv_split(const float* __restrict__ A, __nv_bfloat16* __restrict__ H,
                __nv_bfloat16* __restrict__ L, int n4)
{
    int i = blockIdx.x * 256 + threadIdx.x;
    if (i >= n4) return;
    float4 v = *(const float4*)(A + (size_t)i * 4);
    __nv_bfloat16 h0 = __float2bfloat16(v.x), h1 = __float2bfloat16(v.y);
    __nv_bfloat16 h2 = __float2bfloat16(v.z), h3 = __float2bfloat16(v.w);
    __nv_bfloat16 l0 = __float2bfloat16(v.x - __bfloat162float(h0));
    __nv_bfloat16 l1 = __float2bfloat16(v.y - __bfloat162float(h1));
    __nv_bfloat16 l2 = __float2bfloat16(v.z - __bfloat162float(h2));
    __nv_bfloat16 l3 = __float2bfloat16(v.w - __bfloat162float(h3));
    __nv_bfloat162* Hp = (__nv_bfloat162*)(H + (size_t)i * 4);
    __nv_bfloat162* Lp = (__nv_bfloat162*)(L + (size_t)i * 4);
    Hp[0] = __nv_bfloat162(h0, h1); Hp[1] = __nv_bfloat162(h2, h3);
    Lp[0] = __nv_bfloat162(l0, l1); Lp[1] = __nv_bfloat162(l2, l3);
}

/* W [K][N] row-major -> T [N][K] bf16 hi/lo (k-major for MMA B operand) */
__global__ __launch_bounds__(256)
void conv_split_T(const float* __restrict__ W, __nv_bfloat16* __restrict__ Th,
                  __nv_bfloat16* __restrict__ Tl, int K, int N)
{
    __shared__ float t[32][33];
    int kb = blockIdx.y * 32, nb = blockIdx.x * 32;
    int tx = threadIdx.x & 31, ty = threadIdx.x >> 5;
#pragma unroll
    for (int i = 0; i < 4; i++) {
        int k = ty + 8 * i;
        t[k][tx] = W[(size_t)(kb + k) * N + nb + tx];
    }
    __syncthreads();
#pragma unroll
    for (int i = 0; i < 4; i++) {
        int n = ty + 8 * i;
        float v = t[tx][n];
        __nv_bfloat16 h = __float2bfloat16(v);
        size_t o = (size_t)(nb + n) * K + kb + tx;
        Th[o] = h;
        Tl[o] = __float2bfloat16(v - __bfloat162float(h));
    }
}

/* ---------------- mask dtype detector ---------------------------------- */
__global__ void mask_detect_kernel(const unsigned char* __restrict__ mask)
{
    __shared__ int cnt;
    if (threadIdx.x == 0) cnt = 0;
    __syncthreads();
    int c = 0;
    for (int i = threadIdx.x; i < 16384; i += 256) c += (mask[i] != 0);
    atomicAdd(&cnt, c);
    __syncthreads();
    if (threadIdx.x == 0) g_mask_int = (cnt < 4096) ? 1 : 0;
}

/* ---------------- RoPE -------------------------------------------------- */
__global__ __launch_bounds__(256)
void rope_kernel(const float* __restrict__ fused,
                 float* __restrict__ qr, float* __restrict__ kr)
{
    int idx = blockIdx.x * 256 + threadIdx.x;
    if (idx >= ROWS * NHEAD * 64) return;
    int i   = idx & 63;
    int h   = (idx >> 6) & 7;
    int row = idx >> 9;
    int pos = row & (SEQ - 1);

    float inv = 1.0f / powf(10000.0f, (2.0f * (float)i) / 128.0f);
    float f = (float)pos * inv;
    float s, c;
    sincosf(f, &s, &c);

    const float* base = fused + (size_t)row * N6;
    int off = h * 128 + 2 * i;
    float q0 = base[4*HID + off], q1 = base[4*HID + off + 1];
    float k0 = base[5*HID + off], k1 = base[5*HID + off + 1];
    size_t o = (size_t)row * HID + off;
    qr[o]   = q0 * c - q1 * s;
    qr[o+1] = q1 * c + q0 * s;
    kr[o]   = k0 * c - k1 * s;
    kr[o+1] = k1 * c + k0 * s;
}

/* ---------------- fused 3-way attention (SIMT) -------------------------- */
#define LDT  132
#define LDS_ 33

__global__ __launch_bounds__(256)
void attn_kernel(const unsigned char* __restrict__ mask,
                 const float* __restrict__ bias,
                 float* __restrict__ comb)
{
    extern __shared__ float smf[];
    float* q_s  = smf;
    float* qr_s = q_s  + 32 * LDT;
    float* k_s  = qr_s + 32 * LDT;
    float* kr_s = k_s  + 32 * LDT;
    float* v_s  = kr_s + 32 * LDT;
    float* sp   = v_s  + 32 * LDT;
    float* sr   = sp   + 32 * LDS_;
    float* st   = sr   + 32 * LDS_;
    float* mk   = st   + 32 * LDS_;

    const int b  = blockIdx.z, h = blockIdx.y;
    const int n0 = blockIdx.x * 32;
    const int tid = threadIdx.x;
    const int tx = tid & 15, ty = tid >> 4;
    const int pn = tid >> 3;
    const int pc = (tid & 7) << 2;
    const float inv_s = 1.0f / (float)SEQ;
    const int mint = g_mask_int;

    {
        size_t rowq = (size_t)(b * SEQ + n0 + pn);
        const float* qg  = g_fused + rowq * N6 + 4*HID + h*128;
        const float* qrg = g_qr    + rowq * HID + h*128;
#pragma unroll
        for (int c = 0; c < 4; c++) {
            int d = pc + 32 * c;
            *(float4*)&q_s [pn*LDT + d] = *(const float4*)&qg[d];
            *(float4*)&qr_s[pn*LDT + d] = *(const float4*)&qrg[d];
        }
    }

    float4 accR[4], accT[4], accP[4];
#pragma unroll
    for (int r = 0; r < 4; r++) {
        accR[r] = make_float4(0,0,0,0);
        accT[r] = make_float4(0,0,0,0);
        accP[r] = make_float4(0,0,0,0);
    }

    for (int m0 = 0; m0 < SEQ; m0 += 32) {
        __syncthreads();
        {
            size_t rowm = (size_t)(b * SEQ + m0 + pn);
            const float* kg  = g_fused + rowm * N6 + 5*HID + h*128;
            const float* vg  = g_fused + rowm * N6 + 3*HID + h*128;
            const float* krg = g_kr    + rowm * HID + h*128;
#pragma unroll
            for (int c = 0; c < 4; c++) {
                int d = pc + 32 * c;
                *(float4*)&k_s [pn*LDT + d] = *(const float4*)&kg[d];
                *(float4*)&kr_s[pn*LDT + d] = *(const float4*)&krg[d];
                *(float4*)&v_s [pn*LDT + d] = *(const float4*)&vg[d];
            }
            size_t gi = ((size_t)b * SEQ + (n0 + pn)) * SEQ + m0 + pc;
            float4 bv = *(const float4*)&bias[gi];
            float f0, f1, f2, f3;
            if (mint) {
                int4 mi = *(const int4*)&((const int*)mask)[gi];
                f0 = mi.x ? 1.f : 0.f; f1 = mi.y ? 1.f : 0.f;
                f2 = mi.z ? 1.f : 0.f; f3 = mi.w ? 1.f : 0.f;
            } else {
                uchar4 mu = *(const uchar4*)&mask[gi];
                f0 = mu.x ? 1.f : 0.f; f1 = mu.y ? 1.f : 0.f;
                f2 = mu.z ? 1.f : 0.f; f3 = mu.w ? 1.f : 0.f;
            }
            int sb2 = pn * LDS_ + pc;
            mk[sb2+0] = f0; mk[sb2+1] = f1; mk[sb2+2] = f2; mk[sb2+3] = f3;
            st[sb2+0] = f0 * bv.x; st[sb2+1] = f1 * bv.y;
            st[sb2+2] = f2 * bv.z; st[sb2+3] = f3 * bv.w;
        }
        __syncthreads();

        float dp00=0,dp01=0,dp10=0,dp11=0;
        float dr00=0,dr01=0,dr10=0,dr11=0;
#pragma unroll 4
        for (int d4 = 0; d4 < 32; d4++) {
            int o = d4 << 2;
            float4 a0 = *(const float4*)&q_s[ ty      *LDT + o];
            float4 a1 = *(const float4*)&q_s[(ty+16)  *LDT + o];
            float4 b0 = *(const float4*)&k_s[ tx      *LDT + o];
            float4 b1 = *(const float4*)&k_s[(tx+16)  *LDT + o];
            dp00 += a0.x*b0.x + a0.y*b0.y + a0.z*b0.z + a0.w*b0.w;
            dp01 += a0.x*b1.x + a0.y*b1.y + a0.z*b1.z + a0.w*b1.w;
            dp10 += a1.x*b0.x + a1.y*b0.y + a1.z*b0.z + a1.w*b0.w;
            dp11 += a1.x*b1.x + a1.y*b1.y + a1.z*b1.z + a1.w*b1.w;
            float4 c0 = *(const float4*)&qr_s[ ty     *LDT + o];
            float4 c1 = *(const float4*)&qr_s[(ty+16) *LDT + o];
            float4 e0 = *(const float4*)&kr_s[ tx     *LDT + o];
            float4 e1 = *(const float4*)&kr_s[(tx+16) *LDT + o];
            dr00 += c0.x*e0.x + c0.y*e0.y + c0.z*e0.z + c0.w*e0.w;
            dr01 += c0.x*e1.x + c0.y*e1.y + c0.z*e1.z + c0.w*e1.w;
            dr10 += c1.x*e0.x + c1.y*e0.y + c1.z*e0.z + c1.w*e0.w;
            dr11 += c1.x*e1.x + c1.y*e1.y + c1.z*e1.z + c1.w*e1.w;
        }
        {
            float m00 = mk[ ty     *LDS_ + tx     ];
            float m01 = mk[ ty     *LDS_ + tx + 16];
            float m10 = mk[(ty+16) *LDS_ + tx     ];
            float m11 = mk[(ty+16) *LDS_ + tx + 16];
            sp[ ty     *LDS_ + tx     ] = m00 * fmaxf(dp00, 0.f) * inv_s;
            sp[ ty     *LDS_ + tx + 16] = m01 * fmaxf(dp01, 0.f) * inv_s;
            sp[(ty+16) *LDS_ + tx     ] = m10 * fmaxf(dp10, 0.f) * inv_s;
            sp[(ty+16) *LDS_ + tx + 16] = m11 * fmaxf(dp11, 0.f) * inv_s;
            sr[ ty     *LDS_ + tx     ] = m00 * fmaxf(dr00, 0.f) * inv_s;
            sr[ ty     *LDS_ + tx + 16] = m01 * fmaxf(dr01, 0.f) * inv_s;
            sr[(ty+16) *LDS_ + tx     ] = m10 * fmaxf(dr10, 0.f) * inv_s;
            sr[(ty+16) *LDS_ + tx + 16] = m11 * fmaxf(dr11, 0.f) * inv_s;
        }
        __syncthreads();

#pragma unroll 4
        for (int m = 0; m < 32; m++) {
            float s_r = sr[pn*LDS_ + m];
            float s_t = st[pn*LDS_ + m];
            float s_p = sp[pn*LDS_ + m];
            const float* vp = &v_s[m*LDT + pc];
#pragma unroll
            for (int r = 0; r < 4; r++) {
                float4 v4 = *(const float4*)(vp + 32 * r);
                accR[r].x = fmaf(s_r, v4.x, accR[r].x);
                accR[r].y = fmaf(s_r, v4.y, accR[r].y);
                accR[r].z = fmaf(s_r, v4.z, accR[r].z);
                accR[r].w = fmaf(s_r, v4.w, accR[r].w);
                accT[r].x = fmaf(s_t, v4.x, accT[r].x);
                accT[r].y = fmaf(s_t, v4.y, accT[r].y);
                accT[r].z = fmaf(s_t, v4.z, accT[r].z);
                accT[r].w = fmaf(s_t, v4.w, accT[r].w);
                accP[r].x = fmaf(s_p, v4.x, accP[r].x);
                accP[r].y = fmaf(s_p, v4.y, accP[r].y);
                accP[r].z = fmaf(s_p, v4.z, accP[r].z);
                accP[r].w = fmaf(s_p, v4.w, accP[r].w);
            }
        }
    }

    {
        size_t row = (size_t)(b * SEQ + n0 + pn);
        const float* gate = g_fused + row * N6;
        float* outp = comb + row * N3;
#pragma unroll
        for (int r = 0; r < 4; r++) {
            int d = pc + 32 * r;
            int cR = h*384 +   0 + d;
            int cT = h*384 + 128 + d;
            int cP = h*384 + 256 + d;
            float4 gR = *(const float4*)&gate[cR];
            float4 gT = *(const float4*)&gate[cT];
            float4 gP = *(const float4*)&gate[cP];
            float4 oR, oT, oP;
            oR.x = accR[r].x * gR.x; oR.y = accR[r].y * gR.y;
            oR.z = accR[r].z * gR.z; oR.w = accR[r].w * gR.w;
            oT.x = accT[r].x * gT.x; oT.y = accT[r].y * gT.y;
            oT.z = accT[r].z * gT.z; oT.w = accT[r].w * gT.w;
            oP.x = accP[r].x * gP.x; oP.y = accP[r].y * gP.y;
            oP.z = accP[r].z * gP.z; oP.w = accP[r].w * gP.w;
            *(float4*)&outp[cR] = oR;
            *(float4*)&outp[cT] = oT;
            *(float4*)&outp[cP] = oP;
        }
    }
}

/* ---------------- RMSNorm --------------------------------------------- */
__global__ __launch_bounds__(256)
void rms_kernel(const float* __restrict__ y, const float* __restrict__ w,
                float* __restrict__ out)
{
    __shared__ float sh[8];
    __shared__ float tot;
    int row = blockIdx.x;
    const float* yr = y + (size_t)row * HID;
    float ss = 0.f;
    for (int i = threadIdx.x; i < HID; i += 256) {
        float v = yr[i];
        ss = fmaf(v, v, ss);
    }
#pragma unroll
    for (int o = 16; o > 0; o >>= 1) ss += __shfl_down_sync(0xffffffffu, ss, o);
    if ((threadIdx.x & 31) == 0) sh[threadIdx.x >> 5] = ss;
    __syncthreads();
    if (threadIdx.x == 0) {
        float t = 0.f;
#pragma unroll
        for (int i = 0; i < 8; i++) t += sh[i];
        tot = rsqrtf(t / (float)HID + 1e-6f);
    }
    __syncthreads();
    float r = tot;
    for (int i = threadIdx.x; i < HID; i += 256)
        out[(size_t)row * HID + i] = yr[i] * r * w[i];
}

/* ---------------- launch ----------------------------------------------- */
extern "C" void kernel_launch(void* const* d_in, const int* in_sizes, int n_in,
                              void* d_out, int out_size)
{
    const float*         hidden = (const float*)d_in[0];
    const unsigned char* mask   = (const unsigned char*)d_in[1];
    const float*         bias   = (const float*)d_in[2];
    const float*         Wqkvu  = (const float*)d_in[3];
    const float*         Wout   = (const float*)d_in[4];
    const float*         bout   = (const float*)d_in[5];
    const float*         rmsw   = (const float*)d_in[6];
    float*               out    = (float*)d_out;

    float *fused, *qrp, *krp, *comb, *yp;
    __nv_bfloat16 *ah, *al, *wqh, *wql, *woh, *wol, *ch, *cl;
    cudaGetSymbolAddress((void**)&fused, g_fused);
    cudaGetSymbolAddress((void**)&qrp,   g_qr);
    cudaGetSymbolAddress((void**)&krp,   g_kr);
    cudaGetSymbolAddress((void**)&comb,  g_comb);
    cudaGetSymbolAddress((void**)&yp,    g_y);
    cudaGetSymbolAddress((void**)&ah,  g_ah);
    cudaGetSymbolAddress((void**)&al,  g_al);
    cudaGetSymbolAddress((void**)&wqh, g_wqh);
    cudaGetSymbolAddress((void**)&wql, g_wql);
    cudaGetSymbolAddress((void**)&woh, g_woh);
    cudaGetSymbolAddress((void**)&wol, g_wol);
    cudaGetSymbolAddress((void**)&ch,  g_ch);
    cudaGetSymbolAddress((void**)&cl,  g_cl);

    const size_t ATTN_SMEM = (size_t)(5*32*LDT + 4*32*LDS_) * sizeof(float);
    cudaFuncSetAttribute(attn_kernel, cudaFuncAttributeMaxDynamicSharedMemorySize,
                         (int)ATTN_SMEM);

    mask_detect_kernel<<<1, 256>>>(mask);

    /* bf16x2-split conversions */
    conv_split<<<(ROWS*HID/4 + 255)/256, 256>>>(hidden, ah, al, ROWS*HID/4);
    conv_split_T<<<dim3(N6/32, HID/32), 256>>>(Wqkvu, wqh, wql, HID, N6);
    conv_split_T<<<dim3(HID/32, N3/32), 256>>>(Wout, woh, wol, N3, HID);

    /* fused = silu(hidden @ W_qkvu) via mma.sync */
    mma_gemm<1024, 6144, 0><<<dim3(48, 32), 256>>>(ah, al, wqh, wql,
                                                   fused, nullptr, nullptr);

    rope_kernel<<<(ROWS*NHEAD*64)/256, 256>>>(fused, qrp, krp);

    attn_kernel<<<dim3(SEQ/32, NHEAD, BATCH), 256, ATTN_SMEM>>>(mask, bias, comb);

    /* comb split, then y = comb @ W_out + b_out + hidden via mma.sync */
    conv_split<<<(ROWS*N3/4 + 255)/256, 256>>>(comb, ch, cl, ROWS*N3/4);
    mma_gemm<3072, 1024, 1><<<dim3(8, 32), 256>>>(ch, cl, woh, wol,
                                                  yp, bout, hidden);

    rms_kernel<<<ROWS, 256>>>(yp, rmsw, out);
}

// round 8
// speedup vs baseline: 2.0089x; 1.6363x over previous
#include <cuda_runtime.h>
#include <cuda_bf16.h>
#include <cstdint>
#include <math.h>

#define SEQ   2048
#define BATCH 2
#define HID   1024
#define NHEAD 8
#define HDIM  128
#define ROWS  (BATCH*SEQ)   /* 4096 */
#define N6    (6*HID)       /* 6144 */
#define N3    (3*HID)       /* 3072 */

/* ---------------- scratch (device globals; no allocation allowed) ------- */
__device__ float g_fused[(size_t)ROWS*N6];   /* silu(X @ W_qkvu)   ~100 MB */
__device__ float g_comb[(size_t)ROWS*N3];    /* combined * gated   ~50 MB  */
__device__ float g_y[(size_t)ROWS*HID];
__device__ int   g_mask_int;

/* bf16x2-split operands for mma.sync GEMMs */
__device__ __nv_bfloat16 g_ah[(size_t)ROWS*HID];
__device__ __nv_bfloat16 g_al[(size_t)ROWS*HID];
__device__ __nv_bfloat16 g_wqh[(size_t)N6*HID];
__device__ __nv_bfloat16 g_wql[(size_t)N6*HID];
__device__ __nv_bfloat16 g_woh[(size_t)HID*N3];
__device__ __nv_bfloat16 g_wol[(size_t)HID*N3];
__device__ __nv_bfloat16 g_ch[(size_t)ROWS*N3];
__device__ __nv_bfloat16 g_cl[(size_t)ROWS*N3];

/* attention operands: q/qr/k/kr/v bf16 hi/lo, layout [row][h*128+d] */
__device__ __nv_bfloat16 g_qh[(size_t)ROWS*HID],  g_ql[(size_t)ROWS*HID];
__device__ __nv_bfloat16 g_qrh[(size_t)ROWS*HID], g_qrl[(size_t)ROWS*HID];
__device__ __nv_bfloat16 g_kh[(size_t)ROWS*HID],  g_kl[(size_t)ROWS*HID];
__device__ __nv_bfloat16 g_krh[(size_t)ROWS*HID], g_krl[(size_t)ROWS*HID];
__device__ __nv_bfloat16 g_vh[(size_t)ROWS*HID],  g_vl[(size_t)ROWS*HID];

/* ================= mma.sync helpers ==================================== */
__device__ __forceinline__ uint32_t smem_u32(const void* p) {
    uint32_t a;
    asm("{ .reg .u64 t; cvta.to.shared.u64 t, %1; cvt.u32.u64 %0, t; }"
        : "=r"(a) : "l"(p));
    return a;
}
__device__ __forceinline__ void ldm_x4(uint32_t* r, uint32_t addr) {
    asm volatile("ldmatrix.sync.aligned.m8n8.x4.shared.b16 {%0,%1,%2,%3}, [%4];"
                 : "=r"(r[0]), "=r"(r[1]), "=r"(r[2]), "=r"(r[3]) : "r"(addr));
}
__device__ __forceinline__ void ldm_x2(uint32_t* r, uint32_t addr) {
    asm volatile("ldmatrix.sync.aligned.m8n8.x2.shared.b16 {%0,%1}, [%2];"
                 : "=r"(r[0]), "=r"(r[1]) : "r"(addr));
}
__device__ __forceinline__ void ldm_x4_t(uint32_t* r, uint32_t addr) {
    asm volatile("ldmatrix.sync.aligned.m8n8.x4.trans.shared.b16 {%0,%1,%2,%3}, [%4];"
                 : "=r"(r[0]), "=r"(r[1]), "=r"(r[2]), "=r"(r[3]) : "r"(addr));
}
__device__ __forceinline__ void mma_bf16(float* d,
                                         const uint32_t* a,
                                         uint32_t b0, uint32_t b1) {
    asm volatile("mma.sync.aligned.m16n8k16.row.col.f32.bf16.bf16.f32 "
                 "{%0,%1,%2,%3},{%4,%5,%6,%7},{%8,%9},{%0,%1,%2,%3};"
                 : "+f"(d[0]), "+f"(d[1]), "+f"(d[2]), "+f"(d[3])
                 : "r"(a[0]), "r"(a[1]), "r"(a[2]), "r"(a[3]), "r"(b0), "r"(b1));
}
__device__ __forceinline__ void split_pair(float x0, float x1,
                                           __nv_bfloat16* ph, __nv_bfloat16* pl) {
    __nv_bfloat16 h0 = __float2bfloat16(x0), h1 = __float2bfloat16(x1);
    *(__nv_bfloat162*)ph = __nv_bfloat162(h0, h1);
    *(__nv_bfloat162*)pl = __nv_bfloat162(__float2bfloat16(x0 - __bfloat162float(h0)),
                                          __float2bfloat16(x1 - __bfloat162float(h1)));
}

/* ================= mma.sync GEMM: C[M,N] = A @ B^T (round-6, proven) === */
#define TSTR 40
template<int KDIM, int NDIM, int EPI>
__global__ __launch_bounds__(256)
void mma_gemm(const __nv_bfloat16* __restrict__ Ah, const __nv_bfloat16* __restrict__ Al,
              const __nv_bfloat16* __restrict__ Bh, const __nv_bfloat16* __restrict__ Bl,
              float* __restrict__ C,
              const float* __restrict__ bias, const float* __restrict__ resid)
{
    __shared__ __nv_bfloat16 sAh[128*TSTR], sAl[128*TSTR];
    __shared__ __nv_bfloat16 sBh[128*TSTR], sBl[128*TSTR];

    const int tid  = threadIdx.x;
    const int lane = tid & 31, wid = tid >> 5;
    const int wm = wid >> 2, wn = wid & 3;
    const int m0 = blockIdx.y * 128, n0 = blockIdx.x * 128;

    const uint32_t uAh = smem_u32(sAh), uAl = smem_u32(sAl);
    const uint32_t uBh = smem_u32(sBh), uBl = smem_u32(sBl);

    const int a_r = lane & 15;
    const int a_c = (lane >> 4) * 8;
    const int b_r = (lane & 7) + ((lane >> 4) & 1) * 8;
    const int b_c = ((lane >> 3) & 1) * 8;

    float acc[4][4][4];
#pragma unroll
    for (int i = 0; i < 4; i++)
#pragma unroll
        for (int j = 0; j < 4; j++)
#pragma unroll
            for (int r = 0; r < 4; r++) acc[i][j][r] = 0.f;

    for (int kc = 0; kc < KDIM; kc += 32) {
        __syncthreads();
#pragma unroll
        for (int i = 0; i < 2; i++) {
            int idx = tid + 256 * i;          /* 512 chunks: 128 rows x 4 */
            int row = idx >> 2, seg = (idx & 3) << 3;
            size_t ga = (size_t)(m0 + row) * KDIM + kc + seg;
            size_t gb = (size_t)(n0 + row) * KDIM + kc + seg;
            int so = row * TSTR + seg;
            *(uint4*)&sAh[so] = *(const uint4*)(Ah + ga);
            *(uint4*)&sAl[so] = *(const uint4*)(Al + ga);
            *(uint4*)&sBh[so] = *(const uint4*)(Bh + gb);
            *(uint4*)&sBl[so] = *(const uint4*)(Bl + gb);
        }
        __syncthreads();

#pragma unroll
        for (int k0 = 0; k0 < 32; k0 += 16) {
            uint32_t fAh[4][4], fAl[4][4], fB[2][4];
#pragma unroll
            for (int mt = 0; mt < 4; mt++)
                ldm_x4(fAh[mt], uAh + (uint32_t)((wm*64 + mt*16 + a_r) * TSTR + k0 + a_c) * 2);
#pragma unroll
            for (int bp = 0; bp < 2; bp++)
                ldm_x4(fB[bp], uBh + (uint32_t)((wn*32 + bp*16 + b_r) * TSTR + k0 + b_c) * 2);
#pragma unroll
            for (int mt = 0; mt < 4; mt++)
#pragma unroll
                for (int nt = 0; nt < 4; nt++)
                    mma_bf16(acc[mt][nt], fAh[mt],
                             fB[nt>>1][(nt&1)*2], fB[nt>>1][(nt&1)*2+1]);
#pragma unroll
            for (int mt = 0; mt < 4; mt++)
                ldm_x4(fAl[mt], uAl + (uint32_t)((wm*64 + mt*16 + a_r) * TSTR + k0 + a_c) * 2);
#pragma unroll
            for (int mt = 0; mt < 4; mt++)
#pragma unroll
                for (int nt = 0; nt < 4; nt++)
                    mma_bf16(acc[mt][nt], fAl[mt],
                             fB[nt>>1][(nt&1)*2], fB[nt>>1][(nt&1)*2+1]);
#pragma unroll
            for (int bp = 0; bp < 2; bp++)
                ldm_x4(fB[bp], uBl + (uint32_t)((wn*32 + bp*16 + b_r) * TSTR + k0 + b_c) * 2);
#pragma unroll
            for (int mt = 0; mt < 4; mt++)
#pragma unroll
                for (int nt = 0; nt < 4; nt++)
                    mma_bf16(acc[mt][nt], fAh[mt],
                             fB[nt>>1][(nt&1)*2], fB[nt>>1][(nt&1)*2+1]);
        }
    }

    const int er = lane >> 2, ec = (lane & 3) * 2;
#pragma unroll
    for (int mt = 0; mt < 4; mt++) {
#pragma unroll
        for (int nt = 0; nt < 4; nt++) {
            int col = n0 + wn*32 + nt*8 + ec;
#pragma unroll
            for (int half = 0; half < 2; half++) {
                size_t row = (size_t)(m0 + wm*64 + mt*16 + er + half*8);
                float v0 = acc[mt][nt][half*2 + 0];
                float v1 = acc[mt][nt][half*2 + 1];
                float2 o;
                if (EPI == 0) {
                    o.x = v0 / (1.f + expf(-v0));
                    o.y = v1 / (1.f + expf(-v1));
                } else {
                    size_t rb = row * NDIM + col;
                    o.x = v0 + bias[col+0] + resid[rb+0];
                    o.y = v1 + bias[col+1] + resid[rb+1];
                }
                *(float2*)&C[row * NDIM + col] = o;
            }
        }
    }
}

/* ============ fp32 -> bf16 hi/lo conversions =========================== */
__global__ __launch_bounds__(256)
void conv_split(const float* __restrict__ A, __nv_bfloat16* __restrict__ H,
                __nv_bfloat16* __restrict__ L, int n4)
{
    int i = blockIdx.x * 256 + threadIdx.x;
    if (i >= n4) return;
    float4 v = *(const float4*)(A + (size_t)i * 4);
    split_pair(v.x, v.y, H + (size_t)i*4,     L + (size_t)i*4);
    split_pair(v.z, v.w, H + (size_t)i*4 + 2, L + (size_t)i*4 + 2);
}

__global__ __launch_bounds__(256)
void conv_split_T(const float* __restrict__ W, __nv_bfloat16* __restrict__ Th,
                  __nv_bfloat16* __restrict__ Tl, int K, int N)
{
    __shared__ float t[32][33];
    int kb = blockIdx.y * 32, nb = blockIdx.x * 32;
    int tx = threadIdx.x & 31, ty = threadIdx.x >> 5;
#pragma unroll
    for (int i = 0; i < 4; i++) {
        int k = ty + 8 * i;
        t[k][tx] = W[(size_t)(kb + k) * N + nb + tx];
    }
    __syncthreads();
#pragma unroll
    for (int i = 0; i < 4; i++) {
        int n = ty + 8 * i;
        float v = t[tx][n];
        __nv_bfloat16 h = __float2bfloat16(v);
        size_t o = (size_t)(nb + n) * K + kb + tx;
        Th[o] = h;
        Tl[o] = __float2bfloat16(v - __bfloat162float(h));
    }
}

/* ---------------- mask dtype detector ---------------------------------- */
__global__ void mask_detect_kernel(const unsigned char* __restrict__ mask)
{
    __shared__ int cnt;
    if (threadIdx.x == 0) cnt = 0;
    __syncthreads();
    int c = 0;
    for (int i = threadIdx.x; i < 16384; i += 256) c += (mask[i] != 0);
    atomicAdd(&cnt, c);
    __syncthreads();
    if (threadIdx.x == 0) g_mask_int = (cnt < 4096) ? 1 : 0;
}

/* ---------------- RoPE + bf16 split prep ------------------------------- */
__global__ __launch_bounds__(256)
void rope_split_kernel()
{
    int idx = blockIdx.x * 256 + threadIdx.x;     /* ROWS*NHEAD*64 pairs */
    if (idx >= ROWS * NHEAD * 64) return;
    int i   = idx & 63;
    int h   = (idx >> 6) & 7;
    int row = idx >> 9;
    int pos = row & (SEQ - 1);

    float inv = 1.0f / powf(10000.0f, (2.0f * (float)i) / 128.0f);
    float f = (float)pos * inv;
    float s, c;
    sincosf(f, &s, &c);

    const float* base = g_fused + (size_t)row * N6;
    int off = h * 128 + 2 * i;
    float q0 = base[4*HID + off], q1 = base[4*HID + off + 1];
    float k0 = base[5*HID + off], k1 = base[5*HID + off + 1];
    float v0 = base[3*HID + off], v1 = base[3*HID + off + 1];
    float qr0 = q0 * c - q1 * s, qr1 = q1 * c + q0 * s;
    float kr0 = k0 * c - k1 * s, kr1 = k1 * c + k0 * s;

    size_t o = (size_t)row * HID + off;
    split_pair(q0,  q1,  g_qh  + o, g_ql  + o);
    split_pair(qr0, qr1, g_qrh + o, g_qrl + o);
    split_pair(k0,  k1,  g_kh  + o, g_kl  + o);
    split_pair(kr0, kr1, g_krh + o, g_krl + o);
    split_pair(v0,  v1,  g_vh  + o, g_vl  + o);
}

/* ---------------- tensor-core 3-way attention -------------------------- */
/* block = (b, h, 64 q-rows); stream 32-row m-tiles.                       */
/* Phase A: S = relu(QK^T)*mask*inv_s (plain + rope) via split mma -> smem */
/* Phase B: O[sec] += S[sec] @ V (split), sec order rope/ts/plain.         */
#define KSTR 136   /* K/V/Q smem row stride (bf16): 128 + 8 */
#define SSTR 40    /* S smem row stride: 32 + 8 */

/* smem byte offsets */
#define O_QH   0
#define O_QL   17408
#define O_QRH  34816
#define O_QRL  52224
#define O_KH   69632
#define O_KL   78336
#define O_KRH  87040
#define O_KRL  95744
#define O_VH   104448
#define O_VL   113152
#define O_SRH  121856
#define O_SRL  126976
#define O_STH  132096
#define O_STL  137216
#define O_SPH  142336
#define O_SPL  147456
#define O_MK   152576
#define ASMEM  154624

__global__ __launch_bounds__(256)
void attn_mma(const unsigned char* __restrict__ mask,
              const float* __restrict__ bias,
              float* __restrict__ comb)
{
    extern __shared__ char sm[];
    const uint32_t sb = smem_u32(sm);
    unsigned char* MKb = (unsigned char*)(sm + O_MK);

    const int b = blockIdx.z, h = blockIdx.y, q0 = blockIdx.x * 64;
    const int tid = threadIdx.x, lane = tid & 31, wid = tid >> 5;
    const int wq = wid >> 2, wx = wid & 3;
    const int mint = g_mask_int;
    const float inv_s = 1.0f / (float)SEQ;

    const int a_r = lane & 15, a_c = (lane >> 4) * 8;          /* ldm A / trans-B */
    const int b_r = lane & 7,  b_c = ((lane >> 3) & 1) * 8;    /* ldm x2 B       */
    const int er  = lane >> 2, ec  = (lane & 3) * 2;           /* acc layout     */

    /* persistent Q tiles (q, qr) hi/lo : 64 rows x 128 cols.               */
    /* 16B chunk = 8 bf16; a 128-col row = 16 chunks; 64 rows = 1024 chunks */
#pragma unroll
    for (int i = 0; i < 4; i++) {
        int c = tid + 256 * i;
        int row = c >> 4, seg = (c & 15) * 8;
        size_t g = (size_t)(b * SEQ + q0 + row) * HID + h * 128 + seg;
        int so = (row * KSTR + seg) * 2;
        *(uint4*)(sm + O_QH  + so) = *(const uint4*)&g_qh[g];
        *(uint4*)(sm + O_QL  + so) = *(const uint4*)&g_ql[g];
        *(uint4*)(sm + O_QRH + so) = *(const uint4*)&g_qrh[g];
        *(uint4*)(sm + O_QRL + so) = *(const uint4*)&g_qrl[g];
    }

    float accB[3][2][4][4];
#pragma unroll
    for (int s = 0; s < 3; s++)
#pragma unroll
        for (int t = 0; t < 2; t++)
#pragma unroll
            for (int j = 0; j < 4; j++)
#pragma unroll
                for (int r = 0; r < 4; r++) accB[s][t][j][r] = 0.f;

    for (int m0 = 0; m0 < SEQ; m0 += 32) {
        __syncthreads();   /* previous phase B consumed all tiles */

        /* load K/Kr/V hi/lo tiles: 32 rows x 128 cols = 512 chunks each */
#pragma unroll
        for (int i = 0; i < 2; i++) {
            int c = tid + 256 * i;
            int row = c >> 4, seg = (c & 15) * 8;
            size_t g = (size_t)(b * SEQ + m0 + row) * HID + h * 128 + seg;
            int so = (row * KSTR + seg) * 2;
            *(uint4*)(sm + O_KH  + so) = *(const uint4*)&g_kh[g];
            *(uint4*)(sm + O_KL  + so) = *(const uint4*)&g_kl[g];
            *(uint4*)(sm + O_KRH + so) = *(const uint4*)&g_krh[g];
            *(uint4*)(sm + O_KRL + so) = *(const uint4*)&g_krl[g];
            *(uint4*)(sm + O_VH  + so) = *(const uint4*)&g_vh[g];
            *(uint4*)(sm + O_VL  + so) = *(const uint4*)&g_vl[g];
        }
        /* mask tile + ts scores (mask*bias, split) */
        {
            int n = tid >> 2, seg = (tid & 3) * 8;
            size_t gi = ((size_t)b * SEQ + q0 + n) * SEQ + m0 + seg;
            float4 b0 = *(const float4*)&bias[gi];
            float4 b1 = *(const float4*)&bias[gi + 4];
            float mf[8];
            if (mint) {
                int4 m0i = *(const int4*)&((const int*)mask)[gi];
                int4 m1i = *(const int4*)&((const int*)mask)[gi + 4];
                mf[0]=m0i.x?1.f:0.f; mf[1]=m0i.y?1.f:0.f; mf[2]=m0i.z?1.f:0.f; mf[3]=m0i.w?1.f:0.f;
                mf[4]=m1i.x?1.f:0.f; mf[5]=m1i.y?1.f:0.f; mf[6]=m1i.z?1.f:0.f; mf[7]=m1i.w?1.f:0.f;
            } else {
                uchar4 m0u = *(const uchar4*)&mask[gi];
                uchar4 m1u = *(const uchar4*)&mask[gi + 4];
                mf[0]=m0u.x?1.f:0.f; mf[1]=m0u.y?1.f:0.f; mf[2]=m0u.z?1.f:0.f; mf[3]=m0u.w?1.f:0.f;
                mf[4]=m1u.x?1.f:0.f; mf[5]=m1u.y?1.f:0.f; mf[6]=m1u.z?1.f:0.f; mf[7]=m1u.w?1.f:0.f;
            }
#pragma unroll
            for (int j = 0; j < 8; j++) MKb[n * 32 + seg + j] = (unsigned char)mf[j];
            float bv[8] = {b0.x, b0.y, b0.z, b0.w, b1.x, b1.y, b1.z, b1.w};
            __nv_bfloat16* TH = (__nv_bfloat16*)(sm + O_STH);
            __nv_bfloat16* TL = (__nv_bfloat16*)(sm + O_STL);
#pragma unroll
            for (int j = 0; j < 8; j += 2)
                split_pair(mf[j] * bv[j], mf[j+1] * bv[j+1],
                           TH + n * SSTR + seg + j, TL + n * SSTR + seg + j);
        }
        __syncthreads();

        /* phase A: plain (v=0) then rope (v=1) */
#pragma unroll
        for (int v = 0; v < 2; v++) {
            const uint32_t uQh = sb + (v ? O_QRH : O_QH);
            const uint32_t uQl = sb + (v ? O_QRL : O_QL);
            const uint32_t uKh = sb + (v ? O_KRH : O_KH);
            const uint32_t uKl = sb + (v ? O_KRL : O_KL);
            float acc[2][4];
#pragma unroll
            for (int t = 0; t < 2; t++)
#pragma unroll
                for (int r = 0; r < 4; r++) acc[t][r] = 0.f;

#pragma unroll
            for (int k16 = 0; k16 < 8; k16++) {
                int k0 = k16 * 16;
                uint32_t fAh[2][4], fAl[2][4], fBh[2], fBl[2];
#pragma unroll
                for (int t = 0; t < 2; t++) {
                    ldm_x4(fAh[t], uQh + (uint32_t)((wq*32 + t*16 + a_r) * KSTR + k0 + a_c) * 2);
                    ldm_x4(fAl[t], uQl + (uint32_t)((wq*32 + t*16 + a_r) * KSTR + k0 + a_c) * 2);
                }
                ldm_x2(fBh, uKh + (uint32_t)((wx*8 + b_r) * KSTR + k0 + b_c) * 2);
                ldm_x2(fBl, uKl + (uint32_t)((wx*8 + b_r) * KSTR + k0 + b_c) * 2);
#pragma unroll
                for (int t = 0; t < 2; t++) {
                    mma_bf16(acc[t], fAh[t], fBh[0], fBh[1]);
                    mma_bf16(acc[t], fAl[t], fBh[0], fBh[1]);
                    mma_bf16(acc[t], fAh[t], fBl[0], fBl[1]);
                }
            }
            /* epilogue: relu * mask * inv_s -> split to smem S */
            __nv_bfloat16* SH = (__nv_bfloat16*)(sm + (v ? O_SRH : O_SPH));
            __nv_bfloat16* SL = (__nv_bfloat16*)(sm + (v ? O_SRL : O_SPL));
#pragma unroll
            for (int t = 0; t < 2; t++) {
#pragma unroll
                for (int half = 0; half < 2; half++) {
                    int r = wq*32 + t*16 + er + half*8;
                    int c = wx*8 + ec;
                    float f0 = (float)MKb[r*32 + c];
                    float f1 = (float)MKb[r*32 + c + 1];
                    float s0 = f0 * fmaxf(acc[t][half*2 + 0], 0.f) * inv_s;
                    float s1 = f1 * fmaxf(acc[t][half*2 + 1], 0.f) * inv_s;
                    split_pair(s0, s1, SH + r*SSTR + c, SL + r*SSTR + c);
                }
            }
        }
        __syncthreads();

        /* phase B: O[sec] += S[sec] @ V   (sec 0=rope 1=ts 2=plain) */
        const uint32_t uSH[3] = {sb + O_SRH, sb + O_STH, sb + O_SPH};
        const uint32_t uSL[3] = {sb + O_SRL, sb + O_STL, sb + O_SPL};
        const uint32_t uVh = sb + O_VH, uVl = sb + O_VL;
#pragma unroll
        for (int k16 = 0; k16 < 2; k16++) {
            int k0 = k16 * 16;
            uint32_t fVh[2][4], fVl[2][4];
#pragma unroll
            for (int dh = 0; dh < 2; dh++) {
                ldm_x4_t(fVh[dh], uVh + (uint32_t)((k0 + a_r) * KSTR + wx*32 + dh*16 + a_c) * 2);
                ldm_x4_t(fVl[dh], uVl + (uint32_t)((k0 + a_r) * KSTR + wx*32 + dh*16 + a_c) * 2);
            }
#pragma unroll
            for (int sec = 0; sec < 3; sec++) {
                uint32_t fSh[2][4], fSl[2][4];
#pragma unroll
                for (int t = 0; t < 2; t++) {
                    ldm_x4(fSh[t], uSH[sec] + (uint32_t)((wq*32 + t*16 + a_r) * SSTR + k0 + a_c) * 2);
                    ldm_x4(fSl[t], uSL[sec] + (uint32_t)((wq*32 + t*16 + a_r) * SSTR + k0 + a_c) * 2);
                }
#pragma unroll
                for (int t = 0; t < 2; t++) {
#pragma unroll
                    for (int j = 0; j < 4; j++) {
                        uint32_t bh0 = fVh[j>>1][(j&1)*2], bh1 = fVh[j>>1][(j&1)*2+1];
                        uint32_t bl0 = fVl[j>>1][(j&1)*2], bl1 = fVl[j>>1][(j&1)*2+1];
                        mma_bf16(accB[sec][t][j], fSh[t], bh0, bh1);
                        mma_bf16(accB[sec][t][j], fSl[t], bh0, bh1);
                        mma_bf16(accB[sec][t][j], fSh[t], bl0, bl1);
                    }
                }
            }
        }
    }

    /* final epilogue: * gate, write comb (col = h*384 + sec*128 + d) */
#pragma unroll
    for (int sec = 0; sec < 3; sec++) {
#pragma unroll
        for (int t = 0; t < 2; t++) {
#pragma unroll
            for (int j = 0; j < 4; j++) {
#pragma unroll
                for (int half = 0; half < 2; half++) {
                    int rl = wq*32 + t*16 + er + half*8;
                    size_t grow = (size_t)(b * SEQ + q0 + rl);
                    int d = wx*32 + j*8 + ec;
                    int cx = h*384 + sec*128 + d;
                    float2 g = *(const float2*)&g_fused[grow * N6 + cx];
                    float2 o;
                    o.x = accB[sec][t][j][half*2 + 0] * g.x;
                    o.y = accB[sec][t][j][half*2 + 1] * g.y;
                    *(float2*)&comb[grow * N3 + cx] = o;
                }
            }
        }
    }
}

/* ---------------- RMSNorm --------------------------------------------- */
__global__ __launch_bounds__(256)
void rms_kernel(const float* __restrict__ y, const float* __restrict__ w,
                float* __restrict__ out)
{
    __shared__ float sh[8];
    __shared__ float tot;
    int row = blockIdx.x;
    const float* yr = y + (size_t)row * HID;
    float ss = 0.f;
    for (int i = threadIdx.x; i < HID; i += 256) {
        float v = yr[i];
        ss = fmaf(v, v, ss);
    }
#pragma unroll
    for (int o = 16; o > 0; o >>= 1) ss += __shfl_down_sync(0xffffffffu, ss, o);
    if ((threadIdx.x & 31) == 0) sh[threadIdx.x >> 5] = ss;
    __syncthreads();
    if (threadIdx.x == 0) {
        float t = 0.f;
#pragma unroll
        for (int i = 0; i < 8; i++) t += sh[i];
        tot = rsqrtf(t / (float)HID + 1e-6f);
    }
    __syncthreads();
    float r = tot;
    for (int i = threadIdx.x; i < HID; i += 256)
        out[(size_t)row * HID + i] = yr[i] * r * w[i];
}

/* ---------------- launch ----------------------------------------------- */
extern "C" void kernel_launch(void* const* d_in, const int* in_sizes, int n_in,
                              void* d_out, int out_size)
{
    const float*         hidden = (const float*)d_in[0];
    const unsigned char* mask   = (const unsigned char*)d_in[1];
    const float*         bias   = (const float*)d_in[2];
    const float*         Wqkvu  = (const float*)d_in[3];
    const float*         Wout   = (const float*)d_in[4];
    const float*         bout   = (const float*)d_in[5];
    const float*         rmsw   = (const float*)d_in[6];
    float*               out    = (float*)d_out;

    float *fused, *comb, *yp;
    __nv_bfloat16 *ah, *al, *wqh, *wql, *woh, *wol, *ch, *cl;
    cudaGetSymbolAddress((void**)&fused, g_fused);
    cudaGetSymbolAddress((void**)&comb,  g_comb);
    cudaGetSymbolAddress((void**)&yp,    g_y);
    cudaGetSymbolAddress((void**)&ah,  g_ah);
    cudaGetSymbolAddress((void**)&al,  g_al);
    cudaGetSymbolAddress((void**)&wqh, g_wqh);
    cudaGetSymbolAddress((void**)&wql, g_wql);
    cudaGetSymbolAddress((void**)&woh, g_woh);
    cudaGetSymbolAddress((void**)&wol, g_wol);
    cudaGetSymbolAddress((void**)&ch,  g_ch);
    cudaGetSymbolAddress((void**)&cl,  g_cl);

    cudaFuncSetAttribute(attn_mma, cudaFuncAttributeMaxDynamicSharedMemorySize,
                         ASMEM);

    mask_detect_kernel<<<1, 256>>>(mask);

    /* bf16x2-split conversions */
    conv_split<<<(ROWS*HID/4 + 255)/256, 256>>>(hidden, ah, al, ROWS*HID/4);
    conv_split_T<<<dim3(N6/32, HID/32), 256>>>(Wqkvu, wqh, wql, HID, N6);
    conv_split_T<<<dim3(HID/32, N3/32), 256>>>(Wout, woh, wol, N3, HID);

    /* fused = silu(hidden @ W_qkvu) */
    mma_gemm<1024, 6144, 0><<<dim3(48, 32), 256>>>(ah, al, wqh, wql,
                                                   fused, nullptr, nullptr);

    /* RoPE + bf16 split of q/qr/k/kr/v */
    rope_split_kernel<<<(ROWS*NHEAD*64)/256, 256>>>();

    /* tensor-core 3-way attention -> g_comb (gated) */
    attn_mma<<<dim3(SEQ/64, NHEAD, BATCH), 256, ASMEM>>>(mask, bias, comb);

    /* y = comb @ W_out + b_out + hidden */
    conv_split<<<(ROWS*N3/4 + 255)/256, 256>>>(comb, ch, cl, ROWS*N3/4);
    mma_gemm<3072, 1024, 1><<<dim3(8, 32), 256>>>(ch, cl, woh, wol,
                                                  yp, bout, hidden);

    rms_kernel<<<ROWS, 256>>>(yp, rmsw, out);
}

// round 9
// speedup vs baseline: 2.2586x; 1.1243x over previous
#include <cuda_runtime.h>
#include <cuda_bf16.h>
#include <cstdint>
#include <math.h>

#define SEQ   2048
#define BATCH 2
#define HID   1024
#define NHEAD 8
#define HDIM  128
#define ROWS  (BATCH*SEQ)   /* 4096 */
#define N6    (6*HID)       /* 6144 */
#define N3    (3*HID)       /* 3072 */

/* ---------------- scratch (device globals; no allocation allowed) ------- */
__device__ float g_fused[(size_t)ROWS*N6];   /* silu(X @ W_qkvu)   ~100 MB */
__device__ float g_y[(size_t)ROWS*HID];
__device__ int   g_mask_int;

/* bf16x2-split operands for mma.sync GEMMs */
__device__ __nv_bfloat16 g_ah[(size_t)ROWS*HID];
__device__ __nv_bfloat16 g_al[(size_t)ROWS*HID];
__device__ __nv_bfloat16 g_wqh[(size_t)N6*HID];
__device__ __nv_bfloat16 g_wql[(size_t)N6*HID];
__device__ __nv_bfloat16 g_woh[(size_t)HID*N3];
__device__ __nv_bfloat16 g_wol[(size_t)HID*N3];
__device__ __nv_bfloat16 g_ch[(size_t)ROWS*N3];     /* gated attn out hi */
__device__ __nv_bfloat16 g_cl[(size_t)ROWS*N3];     /* gated attn out lo */

/* attention operands: q/qr/k/kr/v bf16 hi/lo, layout [row][h*128+d] */
__device__ __nv_bfloat16 g_qh[(size_t)ROWS*HID],  g_ql[(size_t)ROWS*HID];
__device__ __nv_bfloat16 g_qrh[(size_t)ROWS*HID], g_qrl[(size_t)ROWS*HID];
__device__ __nv_bfloat16 g_kh[(size_t)ROWS*HID],  g_kl[(size_t)ROWS*HID];
__device__ __nv_bfloat16 g_krh[(size_t)ROWS*HID], g_krl[(size_t)ROWS*HID];
__device__ __nv_bfloat16 g_vh[(size_t)ROWS*HID],  g_vl[(size_t)ROWS*HID];

/* ================= helpers ============================================= */
__device__ __forceinline__ uint32_t smem_u32(const void* p) {
    uint32_t a;
    asm("{ .reg .u64 t; cvta.to.shared.u64 t, %1; cvt.u32.u64 %0, t; }"
        : "=r"(a) : "l"(p));
    return a;
}
__device__ __forceinline__ void cp16(uint32_t saddr, const void* g) {
    asm volatile("cp.async.cg.shared.global [%0], [%1], 16;"
                 :: "r"(saddr), "l"(g));
}
#define CP_COMMIT() asm volatile("cp.async.commit_group;" ::: "memory")
#define CP_WAIT0()  asm volatile("cp.async.wait_group 0;" ::: "memory")
#define CP_WAIT1()  asm volatile("cp.async.wait_group 1;" ::: "memory")

__device__ __forceinline__ void ldm_x4(uint32_t* r, uint32_t addr) {
    asm volatile("ldmatrix.sync.aligned.m8n8.x4.shared.b16 {%0,%1,%2,%3}, [%4];"
                 : "=r"(r[0]), "=r"(r[1]), "=r"(r[2]), "=r"(r[3]) : "r"(addr));
}
__device__ __forceinline__ void ldm_x2(uint32_t* r, uint32_t addr) {
    asm volatile("ldmatrix.sync.aligned.m8n8.x2.shared.b16 {%0,%1}, [%2];"
                 : "=r"(r[0]), "=r"(r[1]) : "r"(addr));
}
__device__ __forceinline__ void ldm_x4_t(uint32_t* r, uint32_t addr) {
    asm volatile("ldmatrix.sync.aligned.m8n8.x4.trans.shared.b16 {%0,%1,%2,%3}, [%4];"
                 : "=r"(r[0]), "=r"(r[1]), "=r"(r[2]), "=r"(r[3]) : "r"(addr));
}
__device__ __forceinline__ void mma_bf16(float* d,
                                         const uint32_t* a,
                                         uint32_t b0, uint32_t b1) {
    asm volatile("mma.sync.aligned.m16n8k16.row.col.f32.bf16.bf16.f32 "
                 "{%0,%1,%2,%3},{%4,%5,%6,%7},{%8,%9},{%0,%1,%2,%3};"
                 : "+f"(d[0]), "+f"(d[1]), "+f"(d[2]), "+f"(d[3])
                 : "r"(a[0]), "r"(a[1]), "r"(a[2]), "r"(a[3]), "r"(b0), "r"(b1));
}
__device__ __forceinline__ void split_pair(float x0, float x1,
                                           __nv_bfloat16* ph, __nv_bfloat16* pl) {
    __nv_bfloat16 h0 = __float2bfloat16(x0), h1 = __float2bfloat16(x1);
    *(__nv_bfloat162*)ph = __nv_bfloat162(h0, h1);
    *(__nv_bfloat162*)pl = __nv_bfloat162(__float2bfloat16(x0 - __bfloat162float(h0)),
                                          __float2bfloat16(x1 - __bfloat162float(h1)));
}

/* ========== cp.async double-buffered mma.sync GEMM: C = A @ B^T ======== */
/* A: [M][KDIM] k-major bf16 hi/lo.  B: [NDIM][KDIM] k-major bf16 hi/lo.   */
/* Block 128x128, BK=32, 8 warps (2m x 4n).  EPI 0: silu. 1: +bias+resid.  */
#define TSTR   40
#define GTILE  10240                    /* 128*TSTR*2 bytes */
#define GSTAGE (4*GTILE)                /* AH AL BH BL      */
#define GSMEM  (2*GSTAGE)               /* 81920            */

template<int KDIM, int NDIM, int EPI>
__global__ __launch_bounds__(256)
void mma_gemm(const __nv_bfloat16* __restrict__ Ah, const __nv_bfloat16* __restrict__ Al,
              const __nv_bfloat16* __restrict__ Bh, const __nv_bfloat16* __restrict__ Bl,
              float* __restrict__ C,
              const float* __restrict__ bias, const float* __restrict__ resid)
{
    extern __shared__ char dsm[];
    const uint32_t sb = smem_u32(dsm);

    const int tid  = threadIdx.x;
    const int lane = tid & 31, wid = tid >> 5;
    const int wm = wid >> 2, wn = wid & 3;
    const int m0 = blockIdx.y * 128, n0 = blockIdx.x * 128;

    const int a_r = lane & 15;
    const int a_c = (lane >> 4) * 8;
    const int b_r = (lane & 7) + ((lane >> 4) & 1) * 8;
    const int b_c = ((lane >> 3) & 1) * 8;

    /* per-thread load coords: 512 chunks per tile = 128 rows x 4 */
    const int l_row = tid >> 1;                     /* rows 0..127, 2 thr/row */
    const int l_seg0 = (tid & 1) << 4;              /* 0 or 16 (2 chunks each)*/

    float acc[4][4][4];
#pragma unroll
    for (int i = 0; i < 4; i++)
#pragma unroll
        for (int j = 0; j < 4; j++)
#pragma unroll
            for (int r = 0; r < 4; r++) acc[i][j][r] = 0.f;

    const int NC = KDIM / 32;

    /* prefetch chunk 0 */
    {
        uint32_t bs = sb;
#pragma unroll
        for (int i = 0; i < 2; i++) {
            int idx = tid + 256 * i;
            int row = idx >> 2, seg = (idx & 3) << 3;
            size_t ga = (size_t)(m0 + row) * KDIM + seg;
            size_t gb = (size_t)(n0 + row) * KDIM + seg;
            uint32_t so = (uint32_t)(row * TSTR + seg) * 2;
            cp16(bs + 0*GTILE + so, Ah + ga);
            cp16(bs + 1*GTILE + so, Al + ga);
            cp16(bs + 2*GTILE + so, Bh + gb);
            cp16(bs + 3*GTILE + so, Bl + gb);
        }
        CP_COMMIT();
    }

    for (int ic = 0; ic < NC; ic++) {
        if (ic + 1 < NC) {
            int kc = (ic + 1) * 32;
            uint32_t bs = sb + ((ic + 1) & 1) * GSTAGE;
#pragma unroll
            for (int i = 0; i < 2; i++) {
                int idx = tid + 256 * i;
                int row = idx >> 2, seg = (idx & 3) << 3;
                size_t ga = (size_t)(m0 + row) * KDIM + kc + seg;
                size_t gb = (size_t)(n0 + row) * KDIM + kc + seg;
                uint32_t so = (uint32_t)(row * TSTR + seg) * 2;
                cp16(bs + 0*GTILE + so, Ah + ga);
                cp16(bs + 1*GTILE + so, Al + ga);
                cp16(bs + 2*GTILE + so, Bh + gb);
                cp16(bs + 3*GTILE + so, Bl + gb);
            }
            CP_COMMIT();
            CP_WAIT1();
        } else {
            CP_WAIT0();
        }
        __syncthreads();

        const uint32_t bs = sb + (ic & 1) * GSTAGE;
        const uint32_t uAh = bs, uAl = bs + GTILE;
        const uint32_t uBh = bs + 2*GTILE, uBl = bs + 3*GTILE;

#pragma unroll
        for (int k0 = 0; k0 < 32; k0 += 16) {
            uint32_t fAh[4][4], fAl[4][4], fB[2][4];
#pragma unroll
            for (int mt = 0; mt < 4; mt++)
                ldm_x4(fAh[mt], uAh + (uint32_t)((wm*64 + mt*16 + a_r) * TSTR + k0 + a_c) * 2);
#pragma unroll
            for (int bp = 0; bp < 2; bp++)
                ldm_x4(fB[bp], uBh + (uint32_t)((wn*32 + bp*16 + b_r) * TSTR + k0 + b_c) * 2);
#pragma unroll
            for (int mt = 0; mt < 4; mt++)
#pragma unroll
                for (int nt = 0; nt < 4; nt++)
                    mma_bf16(acc[mt][nt], fAh[mt],
                             fB[nt>>1][(nt&1)*2], fB[nt>>1][(nt&1)*2+1]);
#pragma unroll
            for (int mt = 0; mt < 4; mt++)
                ldm_x4(fAl[mt], uAl + (uint32_t)((wm*64 + mt*16 + a_r) * TSTR + k0 + a_c) * 2);
#pragma unroll
            for (int mt = 0; mt < 4; mt++)
#pragma unroll
                for (int nt = 0; nt < 4; nt++)
                    mma_bf16(acc[mt][nt], fAl[mt],
                             fB[nt>>1][(nt&1)*2], fB[nt>>1][(nt&1)*2+1]);
#pragma unroll
            for (int bp = 0; bp < 2; bp++)
                ldm_x4(fB[bp], uBl + (uint32_t)((wn*32 + bp*16 + b_r) * TSTR + k0 + b_c) * 2);
#pragma unroll
            for (int mt = 0; mt < 4; mt++)
#pragma unroll
                for (int nt = 0; nt < 4; nt++)
                    mma_bf16(acc[mt][nt], fAh[mt],
                             fB[nt>>1][(nt&1)*2], fB[nt>>1][(nt&1)*2+1]);
        }
        __syncthreads();   /* compute done before next prefetch overwrites */
    }
    (void)l_row; (void)l_seg0;

    const int er = lane >> 2, ec = (lane & 3) * 2;
#pragma unroll
    for (int mt = 0; mt < 4; mt++) {
#pragma unroll
        for (int nt = 0; nt < 4; nt++) {
            int col = n0 + wn*32 + nt*8 + ec;
#pragma unroll
            for (int half = 0; half < 2; half++) {
                size_t row = (size_t)(m0 + wm*64 + mt*16 + er + half*8);
                float v0 = acc[mt][nt][half*2 + 0];
                float v1 = acc[mt][nt][half*2 + 1];
                float2 o;
                if (EPI == 0) {
                    o.x = v0 / (1.f + expf(-v0));
                    o.y = v1 / (1.f + expf(-v1));
                } else {
                    size_t rb = row * NDIM + col;
                    o.x = v0 + bias[col+0] + resid[rb+0];
                    o.y = v1 + bias[col+1] + resid[rb+1];
                }
                *(float2*)&C[row * NDIM + col] = o;
            }
        }
    }
}

/* ============ fp32 -> bf16 hi/lo conversions =========================== */
__global__ __launch_bounds__(256)
void conv_split(const float* __restrict__ A, __nv_bfloat16* __restrict__ H,
                __nv_bfloat16* __restrict__ L, int n4)
{
    int i = blockIdx.x * 256 + threadIdx.x;
    if (i >= n4) return;
    float4 v = *(const float4*)(A + (size_t)i * 4);
    split_pair(v.x, v.y, H + (size_t)i*4,     L + (size_t)i*4);
    split_pair(v.z, v.w, H + (size_t)i*4 + 2, L + (size_t)i*4 + 2);
}

__global__ __launch_bounds__(256)
void conv_split_T(const float* __restrict__ W, __nv_bfloat16* __restrict__ Th,
                  __nv_bfloat16* __restrict__ Tl, int K, int N)
{
    __shared__ float t[32][33];
    int kb = blockIdx.y * 32, nb = blockIdx.x * 32;
    int tx = threadIdx.x & 31, ty = threadIdx.x >> 5;
#pragma unroll
    for (int i = 0; i < 4; i++) {
        int k = ty + 8 * i;
        t[k][tx] = W[(size_t)(kb + k) * N + nb + tx];
    }
    __syncthreads();
#pragma unroll
    for (int i = 0; i < 4; i++) {
        int n = ty + 8 * i;
        float v = t[tx][n];
        __nv_bfloat16 h = __float2bfloat16(v);
        size_t o = (size_t)(nb + n) * K + kb + tx;
        Th[o] = h;
        Tl[o] = __float2bfloat16(v - __bfloat162float(h));
    }
}

/* ---------------- mask dtype detector ---------------------------------- */
__global__ void mask_detect_kernel(const unsigned char* __restrict__ mask)
{
    __shared__ int cnt;
    if (threadIdx.x == 0) cnt = 0;
    __syncthreads();
    int c = 0;
    for (int i = threadIdx.x; i < 16384; i += 256) c += (mask[i] != 0);
    atomicAdd(&cnt, c);
    __syncthreads();
    if (threadIdx.x == 0) g_mask_int = (cnt < 4096) ? 1 : 0;
}

/* ---------------- RoPE + bf16 split prep ------------------------------- */
__global__ __launch_bounds__(256)
void rope_split_kernel()
{
    int idx = blockIdx.x * 256 + threadIdx.x;
    if (idx >= ROWS * NHEAD * 64) return;
    int i   = idx & 63;
    int h   = (idx >> 6) & 7;
    int row = idx >> 9;
    int pos = row & (SEQ - 1);

    float inv = 1.0f / powf(10000.0f, (2.0f * (float)i) / 128.0f);
    float f = (float)pos * inv;
    float s, c;
    sincosf(f, &s, &c);

    const float* base = g_fused + (size_t)row * N6;
    int off = h * 128 + 2 * i;
    float q0 = base[4*HID + off], q1 = base[4*HID + off + 1];
    float k0 = base[5*HID + off], k1 = base[5*HID + off + 1];
    float v0 = base[3*HID + off], v1 = base[3*HID + off + 1];
    float qr0 = q0 * c - q1 * s, qr1 = q1 * c + q0 * s;
    float kr0 = k0 * c - k1 * s, kr1 = k1 * c + k0 * s;

    size_t o = (size_t)row * HID + off;
    split_pair(q0,  q1,  g_qh  + o, g_ql  + o);
    split_pair(qr0, qr1, g_qrh + o, g_qrl + o);
    split_pair(k0,  k1,  g_kh  + o, g_kl  + o);
    split_pair(kr0, kr1, g_krh + o, g_krl + o);
    split_pair(v0,  v1,  g_vh  + o, g_vl  + o);
}

/* ---------------- tensor-core 3-way attention (cp.async pipelined) ----- */
#define KSTR 136   /* K/V/Q smem row stride (bf16): 128 + 8 */
#define SSTR 40    /* S smem row stride: 32 + 8 */
#define KTILE 8704 /* 32*KSTR*2 */

/* smem byte offsets */
#define O_QH   0
#define O_QL   17408
#define O_QRH  34816
#define O_QRL  52224
#define O_KV   69632            /* 2 stages x 6 tiles x 8704 = 104448 */
#define KV_STAGE (6*KTILE)      /* 52224 */
#define O_SRH  174080
#define O_SRL  179200
#define O_STH  184320
#define O_STL  189440
#define O_SPH  194560
#define O_SPL  199680
#define O_MK   204800
#define ASMEM  206848

__global__ __launch_bounds__(256)
void attn_mma(const unsigned char* __restrict__ mask,
              const float* __restrict__ bias,
              __nv_bfloat16* __restrict__ ch, __nv_bfloat16* __restrict__ cl)
{
    extern __shared__ char sm[];
    const uint32_t sb = smem_u32(sm);
    unsigned char* MKb = (unsigned char*)(sm + O_MK);

    const int b = blockIdx.z, h = blockIdx.y, q0 = blockIdx.x * 64;
    const int tid = threadIdx.x, lane = tid & 31, wid = tid >> 5;
    const int wq = wid >> 2, wx = wid & 3;
    const int mint = g_mask_int;
    const float inv_s = 1.0f / (float)SEQ;

    const int a_r = lane & 15, a_c = (lane >> 4) * 8;
    const int b_r = lane & 7,  b_c = ((lane >> 3) & 1) * 8;
    const int er  = lane >> 2, ec  = (lane & 3) * 2;

    /* persistent Q tiles: 64 rows x 128 cols, 1024 chunks per tile */
#pragma unroll
    for (int i = 0; i < 4; i++) {
        int c = tid + 256 * i;
        int row = c >> 4, seg = (c & 15) * 8;
        size_t g = (size_t)(b * SEQ + q0 + row) * HID + h * 128 + seg;
        int so = (row * KSTR + seg) * 2;
        *(uint4*)(sm + O_QH  + so) = *(const uint4*)&g_qh[g];
        *(uint4*)(sm + O_QL  + so) = *(const uint4*)&g_ql[g];
        *(uint4*)(sm + O_QRH + so) = *(const uint4*)&g_qrh[g];
        *(uint4*)(sm + O_QRL + so) = *(const uint4*)&g_qrl[g];
    }

    float accB[3][2][4][4];
#pragma unroll
    for (int s = 0; s < 3; s++)
#pragma unroll
        for (int t = 0; t < 2; t++)
#pragma unroll
            for (int j = 0; j < 4; j++)
#pragma unroll
                for (int r = 0; r < 4; r++) accB[s][t][j][r] = 0.f;

    const int NIT = SEQ / 32;

    /* prefetch KV tiles for m-iter 0 */
    {
        uint32_t bs = sb + O_KV;
#pragma unroll
        for (int i = 0; i < 2; i++) {
            int c = tid + 256 * i;
            int row = c >> 4, seg = (c & 15) * 8;
            size_t g = (size_t)(b * SEQ + row) * HID + h * 128 + seg;
            uint32_t so = (uint32_t)(row * KSTR + seg) * 2;
            cp16(bs + 0*KTILE + so, g_kh  + g);
            cp16(bs + 1*KTILE + so, g_kl  + g);
            cp16(bs + 2*KTILE + so, g_krh + g);
            cp16(bs + 3*KTILE + so, g_krl + g);
            cp16(bs + 4*KTILE + so, g_vh  + g);
            cp16(bs + 5*KTILE + so, g_vl  + g);
        }
        CP_COMMIT();
    }
    __syncthreads();   /* Q tiles visible (also covers first MK/ST writes) */

    for (int it = 0; it < NIT; it++) {
        const int m0 = it * 32;

        /* prefetch next m-tile */
        if (it + 1 < NIT) {
            uint32_t bs = sb + O_KV + ((it + 1) & 1) * KV_STAGE;
            int mn = (it + 1) * 32;
#pragma unroll
            for (int i = 0; i < 2; i++) {
                int c = tid + 256 * i;
                int row = c >> 4, seg = (c & 15) * 8;
                size_t g = (size_t)(b * SEQ + mn + row) * HID + h * 128 + seg;
                uint32_t so = (uint32_t)(row * KSTR + seg) * 2;
                cp16(bs + 0*KTILE + so, g_kh  + g);
                cp16(bs + 1*KTILE + so, g_kl  + g);
                cp16(bs + 2*KTILE + so, g_krh + g);
                cp16(bs + 3*KTILE + so, g_krl + g);
                cp16(bs + 4*KTILE + so, g_vh  + g);
                cp16(bs + 5*KTILE + so, g_vl  + g);
            }
            CP_COMMIT();
        }

        /* mask tile + ts scores (safe: end-of-prev-iter sync) */
        {
            int n = tid >> 2, seg = (tid & 3) * 8;
            size_t gi = ((size_t)b * SEQ + q0 + n) * SEQ + m0 + seg;
            float4 b0 = *(const float4*)&bias[gi];
            float4 b1 = *(const float4*)&bias[gi + 4];
            float mf[8];
            if (mint) {
                int4 m0i = *(const int4*)&((const int*)mask)[gi];
                int4 m1i = *(const int4*)&((const int*)mask)[gi + 4];
                mf[0]=m0i.x?1.f:0.f; mf[1]=m0i.y?1.f:0.f; mf[2]=m0i.z?1.f:0.f; mf[3]=m0i.w?1.f:0.f;
                mf[4]=m1i.x?1.f:0.f; mf[5]=m1i.y?1.f:0.f; mf[6]=m1i.z?1.f:0.f; mf[7]=m1i.w?1.f:0.f;
            } else {
                uchar4 m0u = *(const uchar4*)&mask[gi];
                uchar4 m1u = *(const uchar4*)&mask[gi + 4];
                mf[0]=m0u.x?1.f:0.f; mf[1]=m0u.y?1.f:0.f; mf[2]=m0u.z?1.f:0.f; mf[3]=m0u.w?1.f:0.f;
                mf[4]=m1u.x?1.f:0.f; mf[5]=m1u.y?1.f:0.f; mf[6]=m1u.z?1.f:0.f; mf[7]=m1u.w?1.f:0.f;
            }
#pragma unroll
            for (int j = 0; j < 8; j++) MKb[n * 32 + seg + j] = (unsigned char)mf[j];
            float bv[8] = {b0.x, b0.y, b0.z, b0.w, b1.x, b1.y, b1.z, b1.w};
            __nv_bfloat16* TH = (__nv_bfloat16*)(sm + O_STH);
            __nv_bfloat16* TL = (__nv_bfloat16*)(sm + O_STL);
#pragma unroll
            for (int j = 0; j < 8; j += 2)
                split_pair(mf[j] * bv[j], mf[j+1] * bv[j+1],
                           TH + n * SSTR + seg + j, TL + n * SSTR + seg + j);
        }

        if (it + 1 < NIT) { CP_WAIT1(); } else { CP_WAIT0(); }
        __syncthreads();   /* KV(it) + MK/ST visible */

        const uint32_t kb = sb + O_KV + (it & 1) * KV_STAGE;

        /* phase A: plain (v=0) then rope (v=1) */
#pragma unroll
        for (int v = 0; v < 2; v++) {
            const uint32_t uQh = sb + (v ? O_QRH : O_QH);
            const uint32_t uQl = sb + (v ? O_QRL : O_QL);
            const uint32_t uKh = kb + (v ? 2*KTILE : 0);
            const uint32_t uKl = kb + (v ? 3*KTILE : 1*KTILE);
            float acc[2][4];
#pragma unroll
            for (int t = 0; t < 2; t++)
#pragma unroll
                for (int r = 0; r < 4; r++) acc[t][r] = 0.f;

#pragma unroll
            for (int k16 = 0; k16 < 8; k16++) {
                int k0 = k16 * 16;
                uint32_t fAh[2][4], fAl[2][4], fBh[2], fBl[2];
#pragma unroll
                for (int t = 0; t < 2; t++) {
                    ldm_x4(fAh[t], uQh + (uint32_t)((wq*32 + t*16 + a_r) * KSTR + k0 + a_c) * 2);
                    ldm_x4(fAl[t], uQl + (uint32_t)((wq*32 + t*16 + a_r) * KSTR + k0 + a_c) * 2);
                }
                ldm_x2(fBh, uKh + (uint32_t)((wx*8 + b_r) * KSTR + k0 + b_c) * 2);
                ldm_x2(fBl, uKl + (uint32_t)((wx*8 + b_r) * KSTR + k0 + b_c) * 2);
#pragma unroll
                for (int t = 0; t < 2; t++) {
                    mma_bf16(acc[t], fAh[t], fBh[0], fBh[1]);
                    mma_bf16(acc[t], fAl[t], fBh[0], fBh[1]);
                    mma_bf16(acc[t], fAh[t], fBl[0], fBl[1]);
                }
            }
            __nv_bfloat16* SH = (__nv_bfloat16*)(sm + (v ? O_SRH : O_SPH));
            __nv_bfloat16* SL = (__nv_bfloat16*)(sm + (v ? O_SRL : O_SPL));
#pragma unroll
            for (int t = 0; t < 2; t++) {
#pragma unroll
                for (int half = 0; half < 2; half++) {
                    int r = wq*32 + t*16 + er + half*8;
                    int c = wx*8 + ec;
                    float f0 = (float)MKb[r*32 + c];
                    float f1 = (float)MKb[r*32 + c + 1];
                    float s0 = f0 * fmaxf(acc[t][half*2 + 0], 0.f) * inv_s;
                    float s1 = f1 * fmaxf(acc[t][half*2 + 1], 0.f) * inv_s;
                    split_pair(s0, s1, SH + r*SSTR + c, SL + r*SSTR + c);
                }
            }
        }
        __syncthreads();

        /* phase B: O[sec] += S[sec] @ V   (sec 0=rope 1=ts 2=plain) */
        const uint32_t uSH[3] = {sb + O_SRH, sb + O_STH, sb + O_SPH};
        const uint32_t uSL[3] = {sb + O_SRL, sb + O_STL, sb + O_SPL};
        const uint32_t uVh = kb + 4*KTILE, uVl = kb + 5*KTILE;
#pragma unroll
        for (int k16 = 0; k16 < 2; k16++) {
            int k0 = k16 * 16;
            uint32_t fVh[2][4], fVl[2][4];
#pragma unroll
            for (int dh = 0; dh < 2; dh++) {
                ldm_x4_t(fVh[dh], uVh + (uint32_t)((k0 + a_r) * KSTR + wx*32 + dh*16 + a_c) * 2);
                ldm_x4_t(fVl[dh], uVl + (uint32_t)((k0 + a_r) * KSTR + wx*32 + dh*16 + a_c) * 2);
            }
#pragma unroll
            for (int sec = 0; sec < 3; sec++) {
                uint32_t fSh[2][4], fSl[2][4];
#pragma unroll
                for (int t = 0; t < 2; t++) {
                    ldm_x4(fSh[t], uSH[sec] + (uint32_t)((wq*32 + t*16 + a_r) * SSTR + k0 + a_c) * 2);
                    ldm_x4(fSl[t], uSL[sec] + (uint32_t)((wq*32 + t*16 + a_r) * SSTR + k0 + a_c) * 2);
                }
#pragma unroll
                for (int t = 0; t < 2; t++) {
#pragma unroll
                    for (int j = 0; j < 4; j++) {
                        uint32_t bh0 = fVh[j>>1][(j&1)*2], bh1 = fVh[j>>1][(j&1)*2+1];
                        uint32_t bl0 = fVl[j>>1][(j&1)*2], bl1 = fVl[j>>1][(j&1)*2+1];
                        mma_bf16(accB[sec][t][j], fSh[t], bh0, bh1);
                        mma_bf16(accB[sec][t][j], fSl[t], bh0, bh1);
                        mma_bf16(accB[sec][t][j], fSh[t], bl0, bl1);
                    }
                }
            }
        }
        __syncthreads();   /* all tiles consumed before next prefetch/writes */
    }

    /* final epilogue: * gate, bf16-split directly into ch/cl              */
    /* (fuses the former conv_split pass; col = h*384 + sec*128 + d)       */
#pragma unroll
    for (int sec = 0; sec < 3; sec++) {
#pragma unroll
        for (int t = 0; t < 2; t++) {
#pragma unroll
            for (int j = 0; j < 4; j++) {
#pragma unroll
                for (int half = 0; half < 2; half++) {
                    int rl = wq*32 + t*16 + er + half*8;
                    size_t grow = (size_t)(b * SEQ + q0 + rl);
                    int d = wx*32 + j*8 + ec;
                    int cx = h*384 + sec*128 + d;
                    float2 g = *(const float2*)&g_fused[grow * N6 + cx];
                    float o0 = accB[sec][t][j][half*2 + 0] * g.x;
                    float o1 = accB[sec][t][j][half*2 + 1] * g.y;
                    split_pair(o0, o1, ch + grow * N3 + cx, cl + grow * N3 + cx);
                }
            }
        }
    }
}

/* ---------------- RMSNorm --------------------------------------------- */
__global__ __launch_bounds__(256)
void rms_kernel(const float* __restrict__ y, const float* __restrict__ w,
                float* __restrict__ out)
{
    __shared__ float sh[8];
    __shared__ float tot;
    int row = blockIdx.x;
    const float* yr = y + (size_t)row * HID;
    float ss = 0.f;
    for (int i = threadIdx.x; i < HID; i += 256) {
        float v = yr[i];
        ss = fmaf(v, v, ss);
    }
#pragma unroll
    for (int o = 16; o > 0; o >>= 1) ss += __shfl_down_sync(0xffffffffu, ss, o);
    if ((threadIdx.x & 31) == 0) sh[threadIdx.x >> 5] = ss;
    __syncthreads();
    if (threadIdx.x == 0) {
        float t = 0.f;
#pragma unroll
        for (int i = 0; i < 8; i++) t += sh[i];
        tot = rsqrtf(t / (float)HID + 1e-6f);
    }
    __syncthreads();
    float r = tot;
    for (int i = threadIdx.x; i < HID; i += 256)
        out[(size_t)row * HID + i] = yr[i] * r * w[i];
}

/* ---------------- launch ----------------------------------------------- */
extern "C" void kernel_launch(void* const* d_in, const int* in_sizes, int n_in,
                              void* d_out, int out_size)
{
    const float*         hidden = (const float*)d_in[0];
    const unsigned char* mask   = (const unsigned char*)d_in[1];
    const float*         bias   = (const float*)d_in[2];
    const float*         Wqkvu  = (const float*)d_in[3];
    const float*         Wout   = (const float*)d_in[4];
    const float*         bout   = (const float*)d_in[5];
    const float*         rmsw   = (const float*)d_in[6];
    float*               out    = (float*)d_out;

    float *fused, *yp;
    __nv_bfloat16 *ah, *al, *wqh, *wql, *woh, *wol, *ch, *cl;
    cudaGetSymbolAddress((void**)&fused, g_fused);
    cudaGetSymbolAddress((void**)&yp,    g_y);
    cudaGetSymbolAddress((void**)&ah,  g_ah);
    cudaGetSymbolAddress((void**)&al,  g_al);
    cudaGetSymbolAddress((void**)&wqh, g_wqh);
    cudaGetSymbolAddress((void**)&wql, g_wql);
    cudaGetSymbolAddress((void**)&woh, g_woh);
    cudaGetSymbolAddress((void**)&wol, g_wol);
    cudaGetSymbolAddress((void**)&ch,  g_ch);
    cudaGetSymbolAddress((void**)&cl,  g_cl);

    cudaFuncSetAttribute(attn_mma, cudaFuncAttributeMaxDynamicSharedMemorySize,
                         ASMEM);
    cudaFuncSetAttribute(mma_gemm<1024, 6144, 0>,
                         cudaFuncAttributeMaxDynamicSharedMemorySize, GSMEM);
    cudaFuncSetAttribute(mma_gemm<3072, 1024, 1>,
                         cudaFuncAttributeMaxDynamicSharedMemorySize, GSMEM);

    mask_detect_kernel<<<1, 256>>>(mask);

    /* bf16x2-split conversions */
    conv_split<<<(ROWS*HID/4 + 255)/256, 256>>>(hidden, ah, al, ROWS*HID/4);
    conv_split_T<<<dim3(N6/32, HID/32), 256>>>(Wqkvu, wqh, wql, HID, N6);
    conv_split_T<<<dim3(HID/32, N3/32), 256>>>(Wout, woh, wol, N3, HID);

    /* fused = silu(hidden @ W_qkvu) */
    mma_gemm<1024, 6144, 0><<<dim3(48, 32), 256, GSMEM>>>(ah, al, wqh, wql,
                                                          fused, nullptr, nullptr);

    /* RoPE + bf16 split of q/qr/k/kr/v */
    rope_split_kernel<<<(ROWS*NHEAD*64)/256, 256>>>();

    /* tensor-core 3-way attention -> g_ch/g_cl (gated, pre-split) */
    attn_mma<<<dim3(SEQ/64, NHEAD, BATCH), 256, ASMEM>>>(mask, bias, ch, cl);

    /* y = comb @ W_out + b_out + hidden */
    mma_gemm<3072, 1024, 1><<<dim3(8, 32), 256, GSMEM>>>(ch, cl, woh, wol,
                                                         yp, bout, hidden);

    rms_kernel<<<ROWS, 256>>>(yp, rmsw, out);
}